// round 2
// baseline (speedup 1.0000x reference)
#include <cuda_runtime.h>
#include <math.h>
#include <stdint.h>

#define B_SZ  64
#define DM    768
#define DI    1536
#define NS    16
#define LSEQ  256
#define RWS   16
#define DTR   48

// ---------------- scratch (static device arrays; no allocation) ----------------
__device__ float g_x[B_SZ * DI * LSEQ];          // (b, d, l)   100 MB
__device__ float g_z[B_SZ * LSEQ * DI];          // (b, l, d)   100 MB
__device__ float g_xc[2][B_SZ * DI * LSEQ];      // conv+silu, per dir (dir-local coords)
__device__ float g_xcomp[2][B_SZ * DI * RWS];    // 16-block means
__device__ float g_xdbl[2][B_SZ * RWS * 80];     // x_proj output (dt|B|C)
__device__ float g_y[2][B_SZ * DI * RWS];        // scan output
__device__ float g_gated[B_SZ * LSEQ * DI];      // LN*silu(z) output

// ---------------- SGEMM: C[m,n] = sum_k A[m,k] * W[n,k] ----------------
// BM=BN=128, BK=16, 256 threads, 8x8 register tile per thread.
// MODE 0: plain C row-major (N=768)      [unused currently]
// MODE 1: split epilogue -> g_x / g_z    (in_proj, N=3072)
// MODE 2: A = g_gated internal, C = out  (out_proj, N=768)
template<int MODE>
__global__ void __launch_bounds__(256, 2) sgemm_k(const float* __restrict__ Ain,
                                                  const float* __restrict__ W,
                                                  float* __restrict__ C, int K)
{
    const float* A = (MODE == 2) ? (const float*)g_gated : Ain;

    __shared__ float As[16][128];
    __shared__ float Bs[16][128];

    const int tid = threadIdx.x;
    const int m0 = blockIdx.y * 128;
    const int n0 = blockIdx.x * 128;
    const int tx = tid & 15;       // 0..15 (n)
    const int ty = tid >> 4;       // 0..15 (m)

    const int lr = tid >> 2;       // 0..63 load row
    const int kq = tid & 3;        // 0..3  k-quad

    const float* Aptr = A + (size_t)(m0 + lr) * K + kq * 4;
    const float* Wptr = W + (size_t)(n0 + lr) * K + kq * 4;

    float acc[8][8];
#pragma unroll
    for (int i = 0; i < 8; i++)
#pragma unroll
        for (int j = 0; j < 8; j++) acc[i][j] = 0.f;

    for (int k0 = 0; k0 < K; k0 += 16) {
        float4 a0 = *(const float4*)(Aptr + k0);
        float4 a1 = *(const float4*)(Aptr + (size_t)64 * K + k0);
        float4 b0 = *(const float4*)(Wptr + k0);
        float4 b1 = *(const float4*)(Wptr + (size_t)64 * K + k0);

        As[kq * 4 + 0][lr] = a0.x; As[kq * 4 + 1][lr] = a0.y;
        As[kq * 4 + 2][lr] = a0.z; As[kq * 4 + 3][lr] = a0.w;
        As[kq * 4 + 0][lr + 64] = a1.x; As[kq * 4 + 1][lr + 64] = a1.y;
        As[kq * 4 + 2][lr + 64] = a1.z; As[kq * 4 + 3][lr + 64] = a1.w;
        Bs[kq * 4 + 0][lr] = b0.x; Bs[kq * 4 + 1][lr] = b0.y;
        Bs[kq * 4 + 2][lr] = b0.z; Bs[kq * 4 + 3][lr] = b0.w;
        Bs[kq * 4 + 0][lr + 64] = b1.x; Bs[kq * 4 + 1][lr + 64] = b1.y;
        Bs[kq * 4 + 2][lr + 64] = b1.z; Bs[kq * 4 + 3][lr + 64] = b1.w;
        __syncthreads();

#pragma unroll
        for (int kk = 0; kk < 16; kk++) {
            float ra[8], rb[8];
#pragma unroll
            for (int i = 0; i < 8; i++) ra[i] = As[kk][ty * 8 + i];
#pragma unroll
            for (int j = 0; j < 8; j++) rb[j] = Bs[kk][tx * 8 + j];
#pragma unroll
            for (int i = 0; i < 8; i++)
#pragma unroll
                for (int j = 0; j < 8; j++) acc[i][j] += ra[i] * rb[j];
        }
        __syncthreads();
    }

    // epilogue
#pragma unroll
    for (int i = 0; i < 8; i++) {
        const int m = m0 + ty * 8 + i;
#pragma unroll
        for (int j = 0; j < 8; j++) {
            const int n = n0 + tx * 8 + j;
            const float v = acc[i][j];
            if (MODE == 1) {
                const int b = m >> 8;
                const int l = m & 255;
                if (n < DI) g_x[((size_t)b * DI + n) * LSEQ + l] = v;
                else        g_z[(size_t)m * DI + (n - DI)] = v;
            } else {
                C[(size_t)m * 768 + n] = v;
            }
        }
    }
}

// ---------------- conv + SiLU + 16-block mean (both directions) ----------------
__global__ void __launch_bounds__(256) conv_silu_k(const float* __restrict__ cw,
                                                   const float* __restrict__ cb,
                                                   const float* __restrict__ cwb,
                                                   const float* __restrict__ cbb)
{
    const int d = blockIdx.x;
    const int b = blockIdx.y;
    const int tid = threadIdx.x;

    __shared__ float row[LSEQ];
    const size_t base = (size_t)b * DI + d;
    row[tid] = g_x[base * LSEQ + tid];
    __syncthreads();

    float wf[4], wb[4];
#pragma unroll
    for (int k = 0; k < 4; k++) { wf[k] = cw[d * 4 + k]; wb[k] = cwb[d * 4 + k]; }

    const int l = tid;
    // forward: y[l] = b + sum_k w[k]*x[l-3+k]
    float af = cb[d];
#pragma unroll
    for (int k = 0; k < 4; k++) {
        int idx = l - 3 + k;
        if (idx >= 0) af += wf[k] * row[idx];
    }
    const float sf = af / (1.f + expf(-af));

    // backward (operate in reversed coords): xrev[j] = row[255-j]
    float ab = cbb[d];
#pragma unroll
    for (int k = 0; k < 4; k++) {
        int idx = l - 3 + k;
        if (idx >= 0) ab += wb[k] * row[255 - idx];
    }
    const float sb = ab / (1.f + expf(-ab));

    g_xc[0][base * LSEQ + l] = sf;
    g_xc[1][base * LSEQ + l] = sb;

    // 16-element group means (groups aligned inside warps)
    float mf = sf, mb = sb;
#pragma unroll
    for (int off = 8; off >= 1; off >>= 1) {
        mf += __shfl_xor_sync(0xffffffffu, mf, off);
        mb += __shfl_xor_sync(0xffffffffu, mb, off);
    }
    if ((tid & 15) == 0) {
        g_xcomp[0][base * RWS + (tid >> 4)] = mf * (1.f / 16.f);
        g_xcomp[1][base * RWS + (tid >> 4)] = mb * (1.f / 16.f);
    }
}

// ---------------- x_proj: x_dbl[b,r,e] = sum_d x_comp[b,d,r] * xpw[e,d] ----------------
__global__ void __launch_bounds__(256) xdbl_k(const float* __restrict__ xpw_f,
                                              const float* __restrict__ xpw_b)
{
    const int br = blockIdx.x;          // b*16 + r
    const int dir = blockIdx.y;
    const int b = br >> 4, r = br & 15;

    __shared__ float xs[DI];
    const float* xcomp = g_xcomp[dir];
    for (int i = threadIdx.x; i < DI; i += 256)
        xs[i] = xcomp[((size_t)b * DI + i) * RWS + r];
    __syncthreads();

    const float* xpw = dir ? xpw_b : xpw_f;
    const int warp = threadIdx.x >> 5, lane = threadIdx.x & 31;
    for (int e = warp; e < 80; e += 8) {
        const float* wrow = xpw + (size_t)e * DI;
        float s = 0.f;
        for (int k = lane; k < DI; k += 32) s += xs[k] * wrow[k];
#pragma unroll
        for (int off = 16; off >= 1; off >>= 1) s += __shfl_xor_sync(0xffffffffu, s, off);
        if (lane == 0) g_xdbl[dir][(size_t)br * 80 + e] = s;
    }
}

// ---------------- fused dt_proj + softplus + selective scan ----------------
__global__ void __launch_bounds__(128) scan_k(const float* __restrict__ dtw_f,
                                              const float* __restrict__ dtw_b,
                                              const float* __restrict__ dtb_f,
                                              const float* __restrict__ dtb_b,
                                              const float* __restrict__ Alog_f,
                                              const float* __restrict__ Alog_b)
{
    const int dir = blockIdx.z;
    const int b = blockIdx.y;
    const int d = blockIdx.x * 128 + threadIdx.x;

    __shared__ float xd[RWS * 80];
    const float* xdbl = g_xdbl[dir] + (size_t)b * RWS * 80;
    for (int i = threadIdx.x; i < RWS * 80; i += 128) xd[i] = xdbl[i];
    __syncthreads();

    const float* dtw = (dir ? dtw_b : dtw_f) + (size_t)d * DTR;
    const float* Alog = (dir ? Alog_b : Alog_f) + (size_t)d * NS;
    const float bias = dir ? dtb_b[d] : dtb_f[d];

    float A[NS];
#pragma unroll
    for (int n = 0; n < NS; n++) A[n] = -expf(Alog[n]);

    float u[RWS];
    const float* up = g_xcomp[dir] + ((size_t)b * DI + d) * RWS;
#pragma unroll
    for (int r = 0; r < RWS; r++) u[r] = up[r];

    float h[NS];
#pragma unroll
    for (int n = 0; n < NS; n++) h[n] = 0.f;

    float* yp = g_y[dir] + ((size_t)b * DI + d) * RWS;
#pragma unroll 1
    for (int r = 0; r < RWS; r++) {
        float dt = bias;
#pragma unroll
        for (int rr = 0; rr < DTR; rr++) dt += xd[r * 80 + rr] * dtw[rr];
        const float delta = (dt > 20.f) ? dt : log1pf(expf(dt));
        const float du = delta * u[r];
        float acc = 0.f;
#pragma unroll
        for (int n = 0; n < NS; n++) {
            const float dA = __expf(delta * A[n]);
            h[n] = dA * h[n] + du * xd[r * 80 + 48 + n];
            acc += h[n] * xd[r * 80 + 64 + n];
        }
        yp[r] = acc;
    }
}

// ---------------- combine + LayerNorm + SiLU(z) gate ----------------
__global__ void __launch_bounds__(256) ln_gate_k(const float* __restrict__ Dp,
                                                 const float* __restrict__ Dpb,
                                                 const float* __restrict__ gamma,
                                                 const float* __restrict__ beta)
{
    const int bl = blockIdx.x;           // b*256 + l
    const int b = bl >> 8;
    const int l = bl & 255;
    const int lb = 255 - l;              // backward-coords index
    const int rf = l >> 4, rb = lb >> 4;
    const int tid = threadIdx.x;

    float v[6];
    float s = 0.f, s2 = 0.f;
#pragma unroll
    for (int i = 0; i < 6; i++) {
        const int d = tid + i * 256;
        const size_t base = (size_t)b * DI + d;
        const float cf = g_y[0][base * RWS + rf] + Dp[d] * g_xc[0][base * LSEQ + l];
        const float cbv = g_y[1][base * RWS + rb] + Dpb[d] * g_xc[1][base * LSEQ + lb];
        const float val = 0.5f * (cf + cbv);
        v[i] = val;
        s += val;
        s2 += val * val;
    }

    __shared__ float red[16];
#pragma unroll
    for (int off = 16; off >= 1; off >>= 1) {
        s += __shfl_xor_sync(0xffffffffu, s, off);
        s2 += __shfl_xor_sync(0xffffffffu, s2, off);
    }
    const int warp = tid >> 5, lane = tid & 31;
    if (lane == 0) { red[warp] = s; red[warp + 8] = s2; }
    __syncthreads();
    if (warp == 0) {
        float a = (lane < 8) ? red[lane] : 0.f;
        float c = (lane < 8) ? red[lane + 8] : 0.f;
#pragma unroll
        for (int off = 4; off >= 1; off >>= 1) {
            a += __shfl_xor_sync(0xffffffffu, a, off);
            c += __shfl_xor_sync(0xffffffffu, c, off);
        }
        if (lane == 0) { red[0] = a; red[1] = c; }
    }
    __syncthreads();

    const float mean = red[0] * (1.f / DI);
    const float var = red[1] * (1.f / DI) - mean * mean;
    const float rstd = rsqrtf(var + 1e-5f);

#pragma unroll
    for (int i = 0; i < 6; i++) {
        const int d = tid + i * 256;
        const float g = (v[i] - mean) * rstd * gamma[d] + beta[d];
        const float zv = g_z[(size_t)bl * DI + d];
        const float sz = zv / (1.f + expf(-zv));
        g_gated[(size_t)bl * DI + d] = g * sz;
    }
}

// ---------------- launch ----------------
extern "C" void kernel_launch(void* const* d_in, const int* in_sizes, int n_in,
                              void* d_out, int out_size)
{
    const float* hs    = (const float*)d_in[0];
    const float* inw   = (const float*)d_in[1];
    const float* cw    = (const float*)d_in[2];
    const float* cb    = (const float*)d_in[3];
    const float* cwb   = (const float*)d_in[4];
    const float* cbb   = (const float*)d_in[5];
    const float* xpw   = (const float*)d_in[6];
    const float* xpwb  = (const float*)d_in[7];
    const float* dtw   = (const float*)d_in[8];
    const float* dtwb  = (const float*)d_in[9];
    const float* dtb   = (const float*)d_in[10];
    const float* dtbb  = (const float*)d_in[11];
    const float* Alog  = (const float*)d_in[12];
    const float* Alogb = (const float*)d_in[13];
    const float* Dp    = (const float*)d_in[14];
    const float* Dpb   = (const float*)d_in[15];
    const float* gam   = (const float*)d_in[16];
    const float* bet   = (const float*)d_in[17];
    const float* opw   = (const float*)d_in[18];
    float* out = (float*)d_out;

    // 1) in_proj GEMM: (16384 x 768) x (3072 x 768)^T -> split x/z
    {
        dim3 grid(3072 / 128, 16384 / 128);
        sgemm_k<1><<<grid, 256>>>(hs, inw, nullptr, DM);
    }
    // 2) depthwise conv + SiLU + means (both directions)
    conv_silu_k<<<dim3(DI, B_SZ), 256>>>(cw, cb, cwb, cbb);
    // 3) x_proj
    xdbl_k<<<dim3(B_SZ * RWS, 2), 256>>>(xpw, xpwb);
    // 4) dt_proj + selective scan
    scan_k<<<dim3(DI / 128, B_SZ, 2), 128>>>(dtw, dtwb, dtb, dtbb, Alog, Alogb);
    // 5) combine + LN + gate
    ln_gate_k<<<B_SZ * LSEQ, 256>>>(Dp, Dpb, gam, bet);
    // 6) out_proj GEMM: (16384 x 1536) x (768 x 1536)^T -> d_out
    {
        dim3 grid(768 / 128, 16384 / 128);
        sgemm_k<2><<<grid, 256>>>(nullptr, opw, out, DI);
    }
}

// round 5
// speedup vs baseline: 3.9858x; 3.9858x over previous
#include <cuda_runtime.h>
#include <math.h>
#include <stdint.h>

#define B_SZ  64
#define DM    768
#define DI    1536
#define NS    16
#define LSEQ  256
#define RWS   16
#define DTR   48

// ---------------- scratch (static device arrays; no allocation) ----------------
__device__ float g_x[B_SZ * LSEQ * DI];          // (b, l, d)  row-major
__device__ float g_z[B_SZ * LSEQ * DI];          // (b, l, d)
__device__ float g_xc[2][B_SZ * LSEQ * DI];      // conv+silu, (b, l, d), dir-local l
__device__ float g_xcomp[2][B_SZ * RWS * DI];    // (b, r, d)
__device__ float g_xdbl[2][B_SZ * RWS * 80];     // (b, r, e)
__device__ float g_y[2][B_SZ * RWS * DI];        // (b, r, d)
__device__ float g_gated[B_SZ * LSEQ * DI];      // (b*l, d)

// ---------------- tf32 helpers ----------------
__device__ __forceinline__ float to_tf32(float x) {
    unsigned u;
    asm("cvt.rna.tf32.f32 %0, %1;" : "=r"(u) : "f"(x));
    return __uint_as_float(u);
}

__device__ __forceinline__ void mma_tf32(float* c, const unsigned* a, const unsigned* b) {
    asm volatile(
        "mma.sync.aligned.m16n8k8.row.col.f32.tf32.tf32.f32 "
        "{%0,%1,%2,%3}, {%4,%5,%6,%7}, {%8,%9}, {%0,%1,%2,%3};"
        : "+f"(c[0]), "+f"(c[1]), "+f"(c[2]), "+f"(c[3])
        : "r"(a[0]), "r"(a[1]), "r"(a[2]), "r"(a[3]), "r"(b[0]), "r"(b[1]));
}

// ---------------- tf32 GEMM: C[m,n] = sum_k A[m,k] * W[n,k] ----------------
// Block tile 256(m) x 128(n), BK=16, 512 threads = 16 warps (4m x 4n), warp 64x32.
// MODE 1: split epilogue -> g_x / g_z   (in_proj, N=3072, K=768)
// MODE 2: A = g_gated, C = out (N=768)  (out_proj, K=1536)
template<int MODE>
__global__ void __launch_bounds__(512, 1) mma_gemm(const float* __restrict__ Ain,
                                                   const float* __restrict__ W,
                                                   float* __restrict__ C, int K)
{
    const float* A = (MODE == 2) ? (const float*)g_gated : Ain;

    __shared__ float As[256][20];
    __shared__ float Bs[128][20];

    const int tid = threadIdx.x;
    const int warp = tid >> 5, lane = tid & 31;
    const int m0 = blockIdx.y * 256, n0 = blockIdx.x * 128;
    const int wm = (warp >> 2) * 64;     // 0..192
    const int wn = (warp & 3) * 32;      // 0..96
    const int grp = lane >> 2, tig = lane & 3;

    // global-load index mapping
    const int am0 = tid >> 2;            // A row for i=0 (0..127); i=1 adds 128
    const int kqa = tid & 3;
    const int bn = tid >> 2;             // B row (0..127)
    const int kqb = tid & 3;

    const float* Abase = A + (size_t)(m0 + am0) * K + 4 * kqa;
    const float* Wbase = W + (size_t)(n0 + bn) * K + 4 * kqb;
    const size_t Arow128 = (size_t)128 * K;

    float acc[4][4][4];
#pragma unroll
    for (int i = 0; i < 4; i++)
#pragma unroll
        for (int j = 0; j < 4; j++)
#pragma unroll
            for (int r = 0; r < 4; r++) acc[i][j][r] = 0.f;

    float4 pa0 = *(const float4*)(Abase);
    float4 pa1 = *(const float4*)(Abase + Arow128);
    float4 pb0 = *(const float4*)(Wbase);

    for (int k0 = 0; k0 < K; k0 += 16) {
        // store prefetched chunk (tf32-converted)
        {
            float4 t;
            t.x = to_tf32(pa0.x); t.y = to_tf32(pa0.y); t.z = to_tf32(pa0.z); t.w = to_tf32(pa0.w);
            *(float4*)&As[am0][4 * kqa] = t;
            t.x = to_tf32(pa1.x); t.y = to_tf32(pa1.y); t.z = to_tf32(pa1.z); t.w = to_tf32(pa1.w);
            *(float4*)&As[am0 + 128][4 * kqa] = t;
            t.x = to_tf32(pb0.x); t.y = to_tf32(pb0.y); t.z = to_tf32(pb0.z); t.w = to_tf32(pb0.w);
            *(float4*)&Bs[bn][4 * kqb] = t;
        }
        __syncthreads();

        if (k0 + 16 < K) {
            pa0 = *(const float4*)(Abase + k0 + 16);
            pa1 = *(const float4*)(Abase + Arow128 + k0 + 16);
            pb0 = *(const float4*)(Wbase + k0 + 16);
        }

#pragma unroll
        for (int ks = 0; ks < 2; ks++) {
            const int kk = ks * 8;
            unsigned afr[4][4], bfr[4][2];
#pragma unroll
            for (int mt = 0; mt < 4; mt++) {
                const int rb = wm + mt * 16 + grp;
                afr[mt][0] = __float_as_uint(As[rb][kk + tig]);
                afr[mt][1] = __float_as_uint(As[rb + 8][kk + tig]);
                afr[mt][2] = __float_as_uint(As[rb][kk + tig + 4]);
                afr[mt][3] = __float_as_uint(As[rb + 8][kk + tig + 4]);
            }
#pragma unroll
            for (int nt = 0; nt < 4; nt++) {
                const int nb = wn + nt * 8 + grp;
                bfr[nt][0] = __float_as_uint(Bs[nb][kk + tig]);
                bfr[nt][1] = __float_as_uint(Bs[nb][kk + tig + 4]);
            }
#pragma unroll
            for (int mt = 0; mt < 4; mt++)
#pragma unroll
                for (int nt = 0; nt < 4; nt++)
                    mma_tf32(acc[mt][nt], afr[mt], bfr[nt]);
        }
        __syncthreads();
    }

    // epilogue
#pragma unroll
    for (int mt = 0; mt < 4; mt++) {
#pragma unroll
        for (int nt = 0; nt < 4; nt++) {
            const int m = m0 + wm + mt * 16 + grp;
            const int n = n0 + wn + nt * 8 + 2 * tig;
            float2 v0 = make_float2(acc[mt][nt][0], acc[mt][nt][1]);
            float2 v1 = make_float2(acc[mt][nt][2], acc[mt][nt][3]);
            if (MODE == 1) {
                float* dst = (n0 < DI) ? g_x : g_z;
                const int nn = (n0 < DI) ? n : (n - DI);
                *(float2*)&dst[(size_t)m * DI + nn] = v0;
                *(float2*)&dst[(size_t)(m + 8) * DI + nn] = v1;
            } else {
                *(float2*)&C[(size_t)m * 768 + n] = v0;
                *(float2*)&C[(size_t)(m + 8) * 768 + n] = v1;
            }
        }
    }
}

// ---------------- conv + SiLU + 16-block mean (both directions, tiled) ----------------
// block: (d-tile of 16, b). smem X[256 l][16 d], F for conv results.
__global__ void __launch_bounds__(256) conv_silu_k(const float* __restrict__ cw,
                                                   const float* __restrict__ cb,
                                                   const float* __restrict__ cwb,
                                                   const float* __restrict__ cbb)
{
    __shared__ float X[256][17];
    __shared__ float F[256][17];

    const int d0 = blockIdx.x * 16;
    const int b = blockIdx.y;
    const int tid = threadIdx.x;

    // load X: (b, l, d0:d0+16)
#pragma unroll
    for (int i = 0; i < 4; i++) {
        const int idx = tid + 256 * i;      // 0..1023 float4s
        const int l = idx >> 2, q = idx & 3;
        float4 v = *(const float4*)&g_x[((size_t)b * LSEQ + l) * DI + d0 + 4 * q];
        X[l][4 * q + 0] = v.x; X[l][4 * q + 1] = v.y;
        X[l][4 * q + 2] = v.z; X[l][4 * q + 3] = v.w;
    }
    __syncthreads();

    const int sub = tid >> 4;   // 0..15
    const int d = tid & 15;
    const int dg = d0 + d;

    // ---- forward ----
    {
        float w[4];
#pragma unroll
        for (int k = 0; k < 4; k++) w[k] = cw[dg * 4 + k];
        const float bias = cb[dg];
#pragma unroll
        for (int i = 0; i < 16; i++) {
            const int l = i * 16 + sub;
            float a = bias;
#pragma unroll
            for (int k = 0; k < 4; k++) {
                const int idx = l - 3 + k;
                if (idx >= 0) a += w[k] * X[idx][d];
            }
            const float s = __fdividef(a, 1.f + __expf(-a));
            F[l][d] = s;
            g_xc[0][((size_t)b * LSEQ + l) * DI + dg] = s;
        }
    }
    __syncthreads();
    {
        const int r = tid >> 4;
        float s = 0.f;
#pragma unroll
        for (int j = 0; j < 16; j++) s += F[16 * r + j][d];
        g_xcomp[0][((size_t)b * RWS + r) * DI + dg] = s * (1.f / 16.f);
    }
    __syncthreads();

    // ---- backward (dir-local coords: xrev[j] = X[255-j]) ----
    {
        float w[4];
#pragma unroll
        for (int k = 0; k < 4; k++) w[k] = cwb[dg * 4 + k];
        const float bias = cbb[dg];
#pragma unroll
        for (int i = 0; i < 16; i++) {
            const int l = i * 16 + sub;
            float a = bias;
#pragma unroll
            for (int k = 0; k < 4; k++) {
                const int idx = l - 3 + k;
                if (idx >= 0) a += w[k] * X[255 - idx][d];
            }
            const float s = __fdividef(a, 1.f + __expf(-a));
            F[l][d] = s;
            g_xc[1][((size_t)b * LSEQ + l) * DI + dg] = s;
        }
    }
    __syncthreads();
    {
        const int r = tid >> 4;
        float s = 0.f;
#pragma unroll
        for (int j = 0; j < 16; j++) s += F[16 * r + j][d];
        g_xcomp[1][((size_t)b * RWS + r) * DI + dg] = s * (1.f / 16.f);
    }
}

// ---------------- x_proj: 4 r per block ----------------
__global__ void __launch_bounds__(256) xdbl_k(const float* __restrict__ xpw_f,
                                              const float* __restrict__ xpw_b)
{
    __shared__ float xs[4 * DI];
    const int dir = blockIdx.y;
    const int b = blockIdx.x >> 2;
    const int rq = blockIdx.x & 3;       // r = rq*4 + j

    const float* src = g_xcomp[dir] + ((size_t)b * RWS + rq * 4) * DI;
    for (int i = threadIdx.x; i < 4 * DI; i += 256) xs[i] = src[i];
    __syncthreads();

    const float* xpw = dir ? xpw_b : xpw_f;
    const int warp = threadIdx.x >> 5, lane = threadIdx.x & 31;
    for (int e = warp; e < 80; e += 8) {
        const float* wrow = xpw + (size_t)e * DI;
        float s0 = 0.f, s1 = 0.f, s2 = 0.f, s3 = 0.f;
        for (int k = lane; k < DI; k += 32) {
            const float w = wrow[k];
            s0 += w * xs[k];
            s1 += w * xs[DI + k];
            s2 += w * xs[2 * DI + k];
            s3 += w * xs[3 * DI + k];
        }
#pragma unroll
        for (int off = 16; off >= 1; off >>= 1) {
            s0 += __shfl_xor_sync(0xffffffffu, s0, off);
            s1 += __shfl_xor_sync(0xffffffffu, s1, off);
            s2 += __shfl_xor_sync(0xffffffffu, s2, off);
            s3 += __shfl_xor_sync(0xffffffffu, s3, off);
        }
        if (lane < 4) {
            const float v = (lane == 0) ? s0 : (lane == 1) ? s1 : (lane == 2) ? s2 : s3;
            g_xdbl[dir][((size_t)b * RWS + rq * 4 + lane) * 80 + e] = v;
        }
    }
}

// ---------------- fused dt_proj + softplus + selective scan ----------------
__global__ void __launch_bounds__(128) scan_k(const float* __restrict__ dtw_f,
                                              const float* __restrict__ dtw_b,
                                              const float* __restrict__ dtb_f,
                                              const float* __restrict__ dtb_b,
                                              const float* __restrict__ Alog_f,
                                              const float* __restrict__ Alog_b)
{
    __shared__ float xd[RWS * 80];
    __shared__ float dtws[128][49];

    const int dir = blockIdx.z;
    const int b = blockIdx.y;
    const int d0 = blockIdx.x * 128;
    const int tid = threadIdx.x;
    const int d = d0 + tid;

    const float* xdbl = g_xdbl[dir] + (size_t)b * RWS * 80;
    for (int i = tid; i < RWS * 80; i += 128) xd[i] = xdbl[i];

    const float* dtw = dir ? dtw_b : dtw_f;
    for (int idx = tid; idx < 128 * DTR; idx += 128) {
        const int row = idx / DTR, col = idx % DTR;
        dtws[row][col] = dtw[(size_t)d0 * DTR + idx];
    }
    __syncthreads();

    const float* Alog = (dir ? Alog_b : Alog_f) + (size_t)d * NS;
    const float bias = dir ? dtb_b[d] : dtb_f[d];

    float A[NS];
#pragma unroll
    for (int n = 0; n < NS; n++) A[n] = -expf(Alog[n]);

    // chain validity: A[n] == (n+1)*A[0] (true for the Mamba A_log init)
    const float A0 = A[0];
    bool chain = true;
#pragma unroll
    for (int n = 1; n < NS; n++)
        chain = chain && (fabsf(A[n] - (float)(n + 1) * A0) <= 1e-4f * fabsf(A[n]));

    float u[RWS];
    const float* up = g_xcomp[dir] + (size_t)b * RWS * DI + d;
#pragma unroll
    for (int r = 0; r < RWS; r++) u[r] = up[(size_t)r * DI];

    float h[NS];
#pragma unroll
    for (int n = 0; n < NS; n++) h[n] = 0.f;

    float* yp = g_y[dir] + (size_t)b * RWS * DI + d;
#pragma unroll 1
    for (int r = 0; r < RWS; r++) {
        float dt = bias;
#pragma unroll
        for (int rr = 0; rr < DTR; rr++) dt += xd[r * 80 + rr] * dtws[tid][rr];
        // stable softplus
        const float delta = fmaxf(dt, 0.f) + log1pf(__expf(-fabsf(dt)));
        const float du = delta * u[r];
        const float q = __expf(delta * A0);
        float p = 1.f;
        float acc = 0.f;
#pragma unroll
        for (int n = 0; n < NS; n++) {
            float dA;
            if (chain) { p *= q; dA = p; }
            else       { dA = __expf(delta * A[n]); }
            h[n] = dA * h[n] + du * xd[r * 80 + 48 + n];
            acc += h[n] * xd[r * 80 + 64 + n];
        }
        yp[(size_t)r * DI] = acc;
    }
}

// ---------------- combine + LayerNorm + SiLU(z) gate ----------------
__global__ void __launch_bounds__(256) ln_gate_k(const float* __restrict__ Dp,
                                                 const float* __restrict__ Dpb,
                                                 const float* __restrict__ gamma,
                                                 const float* __restrict__ beta)
{
    const int bl = blockIdx.x;           // b*256 + l
    const int b = bl >> 8;
    const int l = bl & 255;
    const int lb = 255 - l;
    const int rf = l >> 4, rb = lb >> 4;
    const int tid = threadIdx.x;

    const float* xcf = g_xc[0] + ((size_t)b * LSEQ + l) * DI;
    const float* xcb = g_xc[1] + ((size_t)b * LSEQ + lb) * DI;
    const float* yf = g_y[0] + ((size_t)b * RWS + rf) * DI;
    const float* yb = g_y[1] + ((size_t)b * RWS + rb) * DI;

    float v[6];
    float s = 0.f, s2 = 0.f;
#pragma unroll
    for (int i = 0; i < 6; i++) {
        const int d = tid + i * 256;
        const float cf = yf[d] + Dp[d] * xcf[d];
        const float cbv = yb[d] + Dpb[d] * xcb[d];
        const float val = 0.5f * (cf + cbv);
        v[i] = val;
        s += val;
        s2 += val * val;
    }

    __shared__ float red[16];
#pragma unroll
    for (int off = 16; off >= 1; off >>= 1) {
        s += __shfl_xor_sync(0xffffffffu, s, off);
        s2 += __shfl_xor_sync(0xffffffffu, s2, off);
    }
    const int warp = tid >> 5, lane = tid & 31;
    if (lane == 0) { red[warp] = s; red[warp + 8] = s2; }
    __syncthreads();
    if (warp == 0) {
        float a = (lane < 8) ? red[lane] : 0.f;
        float c = (lane < 8) ? red[lane + 8] : 0.f;
#pragma unroll
        for (int off = 4; off >= 1; off >>= 1) {
            a += __shfl_xor_sync(0xffffffffu, a, off);
            c += __shfl_xor_sync(0xffffffffu, c, off);
        }
        if (lane == 0) { red[0] = a; red[1] = c; }
    }
    __syncthreads();

    const float mean = red[0] * (1.f / DI);
    const float var = red[1] * (1.f / DI) - mean * mean;
    const float rstd = rsqrtf(var + 1e-5f);

#pragma unroll
    for (int i = 0; i < 6; i++) {
        const int d = tid + i * 256;
        const float g = (v[i] - mean) * rstd * gamma[d] + beta[d];
        const float zv = g_z[(size_t)bl * DI + d];
        const float sz = __fdividef(zv, 1.f + __expf(-zv));
        g_gated[(size_t)bl * DI + d] = g * sz;
    }
}

// ---------------- launch ----------------
extern "C" void kernel_launch(void* const* d_in, const int* in_sizes, int n_in,
                              void* d_out, int out_size)
{
    const float* hs    = (const float*)d_in[0];
    const float* inw   = (const float*)d_in[1];
    const float* cw    = (const float*)d_in[2];
    const float* cb    = (const float*)d_in[3];
    const float* cwb   = (const float*)d_in[4];
    const float* cbb   = (const float*)d_in[5];
    const float* xpw   = (const float*)d_in[6];
    const float* xpwb  = (const float*)d_in[7];
    const float* dtw   = (const float*)d_in[8];
    const float* dtwb  = (const float*)d_in[9];
    const float* dtb   = (const float*)d_in[10];
    const float* dtbb  = (const float*)d_in[11];
    const float* Alog  = (const float*)d_in[12];
    const float* Alogb = (const float*)d_in[13];
    const float* Dp    = (const float*)d_in[14];
    const float* Dpb   = (const float*)d_in[15];
    const float* gam   = (const float*)d_in[16];
    const float* bet   = (const float*)d_in[17];
    const float* opw   = (const float*)d_in[18];
    float* out = (float*)d_out;

    // 1) in_proj: (16384 x 768) x (3072 x 768)^T -> g_x | g_z
    mma_gemm<1><<<dim3(3072 / 128, 16384 / 256), 512>>>(hs, inw, nullptr, DM);
    // 2) depthwise conv + SiLU + block means (both directions)
    conv_silu_k<<<dim3(DI / 16, B_SZ), 256>>>(cw, cb, cwb, cbb);
    // 3) x_proj
    xdbl_k<<<dim3(B_SZ * 4, 2), 256>>>(xpw, xpwb);
    // 4) dt_proj + selective scan
    scan_k<<<dim3(DI / 128, B_SZ, 2), 128>>>(dtw, dtwb, dtb, dtbb, Alog, Alogb);
    // 5) combine + LN + gate
    ln_gate_k<<<B_SZ * LSEQ, 256>>>(Dp, Dpb, gam, bet);
    // 6) out_proj: (16384 x 1536) x (768 x 1536)^T -> d_out
    mma_gemm<2><<<dim3(768 / 128, 16384 / 256), 512>>>(nullptr, opw, out, DI);
}

// round 10
// speedup vs baseline: 5.7354x; 1.4390x over previous
#include <cuda_runtime.h>
#include <cuda_fp16.h>
#include <math.h>
#include <stdint.h>

#define B_SZ  64
#define DM    768
#define DI    1536
#define NS    16
#define LSEQ  256
#define RWS   16
#define DTR   48

// ---------------- scratch (static device arrays; no allocation) ----------------
__device__ float g_x[B_SZ * LSEQ * DI];          // (b, l, d)
__device__ float g_z[B_SZ * LSEQ * DI];          // (b, l, d)
__device__ float g_xc[2][B_SZ * LSEQ * DI];      // conv+silu, (b, l, d), dir-local l
__device__ float g_xcomp[2][B_SZ * RWS * DI];    // (b, r, d)
__device__ float g_xdbl[2][B_SZ * RWS * 80];     // (b, r, e)
__device__ float g_y[2][B_SZ * RWS * DI];        // (b, r, d)
__device__ __half g_gated[B_SZ * LSEQ * DI];     // (b*l, d)  -- half, feeds out_proj

// ---------------- fp16 mma helper ----------------
__device__ __forceinline__ void mma_f16(float* c, const unsigned* a, const unsigned* b) {
    asm volatile(
        "mma.sync.aligned.m16n8k16.row.col.f32.f16.f16.f32 "
        "{%0,%1,%2,%3}, {%4,%5,%6,%7}, {%8,%9}, {%0,%1,%2,%3};"
        : "+f"(c[0]), "+f"(c[1]), "+f"(c[2]), "+f"(c[3])
        : "r"(a[0]), "r"(a[1]), "r"(a[2]), "r"(a[3]), "r"(b[0]), "r"(b[1]));
}

__device__ __forceinline__ unsigned pack_half2(float x, float y) {
    __half2 h = __floats2half2_rn(x, y);
    return *(unsigned*)&h;
}

// ---------------- fp16 GEMM: C[m,n] = sum_k A[m,k] * W[n,k] ----------------
// Block tile 256(m) x 128(n), BK=16, 512 threads = 16 warps (4m x 4n), warp 64x32.
// MODE 1: A fp32 (hidden_states); split epilogue -> g_x / g_z  (in_proj, N=3072, K=768)
// MODE 2: A = g_gated (half), C = out (N=768)                   (out_proj, K=1536)
template<int MODE>
__global__ void __launch_bounds__(512, 1) mma_gemm(const float* __restrict__ Ain,
                                                   const float* __restrict__ W,
                                                   float* __restrict__ C, int K)
{
    __shared__ __half As[256][24];
    __shared__ __half Bs[128][24];

    const int tid = threadIdx.x;
    const int warp = tid >> 5, lane = tid & 31;
    const int m0 = blockIdx.y * 256, n0 = blockIdx.x * 128;
    const int wm = (warp >> 2) * 64;     // 0..192
    const int wn = (warp & 3) * 32;      // 0..96
    const int grp = lane >> 2, tig = lane & 3;

    const int am0 = tid >> 2;            // A row i=0 (0..127); i=1 adds 128
    const int kq = tid & 3;              // k-quad (4 floats each)
    const int bn = tid >> 2;             // B row (0..127)

    const float* Abase_f = Ain + (size_t)(m0 + am0) * K + 4 * kq;
    const __half* Abase_h = (const __half*)g_gated + (size_t)(m0 + am0) * K + 4 * kq;
    const float* Wbase = W + (size_t)(n0 + bn) * K + 4 * kq;
    const size_t Arow128 = (size_t)128 * K;

    float acc[4][4][4];
#pragma unroll
    for (int i = 0; i < 4; i++)
#pragma unroll
        for (int j = 0; j < 4; j++)
#pragma unroll
            for (int r = 0; r < 4; r++) acc[i][j][r] = 0.f;

    // prefetch registers
    float4 pa0f, pa1f; uint2 pa0h, pa1h; float4 pb0;
    if (MODE == 1) {
        pa0f = *(const float4*)(Abase_f);
        pa1f = *(const float4*)(Abase_f + Arow128);
    } else {
        pa0h = *(const uint2*)(Abase_h);
        pa1h = *(const uint2*)(Abase_h + Arow128);
    }
    pb0 = *(const float4*)(Wbase);

    for (int k0 = 0; k0 < K; k0 += 16) {
        // store prefetched chunk into smem (half)
        if (MODE == 1) {
            *(unsigned*)&As[am0][4 * kq]       = pack_half2(pa0f.x, pa0f.y);
            *(unsigned*)&As[am0][4 * kq + 2]   = pack_half2(pa0f.z, pa0f.w);
            *(unsigned*)&As[am0 + 128][4 * kq]     = pack_half2(pa1f.x, pa1f.y);
            *(unsigned*)&As[am0 + 128][4 * kq + 2] = pack_half2(pa1f.z, pa1f.w);
        } else {
            *(uint2*)&As[am0][4 * kq] = pa0h;
            *(uint2*)&As[am0 + 128][4 * kq] = pa1h;
        }
        *(unsigned*)&Bs[bn][4 * kq]     = pack_half2(pb0.x, pb0.y);
        *(unsigned*)&Bs[bn][4 * kq + 2] = pack_half2(pb0.z, pb0.w);
        __syncthreads();

        if (k0 + 16 < K) {
            if (MODE == 1) {
                pa0f = *(const float4*)(Abase_f + k0 + 16);
                pa1f = *(const float4*)(Abase_f + Arow128 + k0 + 16);
            } else {
                pa0h = *(const uint2*)(Abase_h + k0 + 16);
                pa1h = *(const uint2*)(Abase_h + Arow128 + k0 + 16);
            }
            pb0 = *(const float4*)(Wbase + k0 + 16);
        }

        // fragments for full BK=16 (one m16n8k16 per (m,n) pair)
        unsigned afr[4][4], bfr[4][2];
#pragma unroll
        for (int mt = 0; mt < 4; mt++) {
            const int rb = wm + mt * 16 + grp;
            afr[mt][0] = *(const unsigned*)&As[rb][2 * tig];
            afr[mt][1] = *(const unsigned*)&As[rb + 8][2 * tig];
            afr[mt][2] = *(const unsigned*)&As[rb][2 * tig + 8];
            afr[mt][3] = *(const unsigned*)&As[rb + 8][2 * tig + 8];
        }
#pragma unroll
        for (int nt = 0; nt < 4; nt++) {
            const int nb = wn + nt * 8 + grp;
            bfr[nt][0] = *(const unsigned*)&Bs[nb][2 * tig];
            bfr[nt][1] = *(const unsigned*)&Bs[nb][2 * tig + 8];
        }
#pragma unroll
        for (int mt = 0; mt < 4; mt++)
#pragma unroll
            for (int nt = 0; nt < 4; nt++)
                mma_f16(acc[mt][nt], afr[mt], bfr[nt]);
        __syncthreads();
    }

    // epilogue
#pragma unroll
    for (int mt = 0; mt < 4; mt++) {
#pragma unroll
        for (int nt = 0; nt < 4; nt++) {
            const int m = m0 + wm + mt * 16 + grp;
            const int n = n0 + wn + nt * 8 + 2 * tig;
            float2 v0 = make_float2(acc[mt][nt][0], acc[mt][nt][1]);
            float2 v1 = make_float2(acc[mt][nt][2], acc[mt][nt][3]);
            if (MODE == 1) {
                float* dst = (n0 < DI) ? g_x : g_z;
                const int nn = (n0 < DI) ? n : (n - DI);
                *(float2*)&dst[(size_t)m * DI + nn] = v0;
                *(float2*)&dst[(size_t)(m + 8) * DI + nn] = v1;
            } else {
                *(float2*)&C[(size_t)m * 768 + n] = v0;
                *(float2*)&C[(size_t)(m + 8) * 768 + n] = v1;
            }
        }
    }
}

// ---------------- conv + SiLU + 16-block mean (both directions, tiled) ----------------
__global__ void __launch_bounds__(256) conv_silu_k(const float* __restrict__ cw,
                                                   const float* __restrict__ cb,
                                                   const float* __restrict__ cwb,
                                                   const float* __restrict__ cbb)
{
    __shared__ float X[256][17];
    __shared__ float F[256][17];

    const int d0 = blockIdx.x * 16;
    const int b = blockIdx.y;
    const int tid = threadIdx.x;

#pragma unroll
    for (int i = 0; i < 4; i++) {
        const int idx = tid + 256 * i;
        const int l = idx >> 2, q = idx & 3;
        float4 v = *(const float4*)&g_x[((size_t)b * LSEQ + l) * DI + d0 + 4 * q];
        X[l][4 * q + 0] = v.x; X[l][4 * q + 1] = v.y;
        X[l][4 * q + 2] = v.z; X[l][4 * q + 3] = v.w;
    }
    __syncthreads();

    const int sub = tid >> 4;
    const int d = tid & 15;
    const int dg = d0 + d;

    {
        float w[4];
#pragma unroll
        for (int k = 0; k < 4; k++) w[k] = cw[dg * 4 + k];
        const float bias = cb[dg];
#pragma unroll
        for (int i = 0; i < 16; i++) {
            const int l = i * 16 + sub;
            float a = bias;
#pragma unroll
            for (int k = 0; k < 4; k++) {
                const int idx = l - 3 + k;
                if (idx >= 0) a += w[k] * X[idx][d];
            }
            const float s = __fdividef(a, 1.f + __expf(-a));
            F[l][d] = s;
            g_xc[0][((size_t)b * LSEQ + l) * DI + dg] = s;
        }
    }
    __syncthreads();
    {
        const int r = tid >> 4;
        float s = 0.f;
#pragma unroll
        for (int j = 0; j < 16; j++) s += F[16 * r + j][d];
        g_xcomp[0][((size_t)b * RWS + r) * DI + dg] = s * (1.f / 16.f);
    }
    __syncthreads();

    {
        float w[4];
#pragma unroll
        for (int k = 0; k < 4; k++) w[k] = cwb[dg * 4 + k];
        const float bias = cbb[dg];
#pragma unroll
        for (int i = 0; i < 16; i++) {
            const int l = i * 16 + sub;
            float a = bias;
#pragma unroll
            for (int k = 0; k < 4; k++) {
                const int idx = l - 3 + k;
                if (idx >= 0) a += w[k] * X[255 - idx][d];
            }
            const float s = __fdividef(a, 1.f + __expf(-a));
            F[l][d] = s;
            g_xc[1][((size_t)b * LSEQ + l) * DI + dg] = s;
        }
    }
    __syncthreads();
    {
        const int r = tid >> 4;
        float s = 0.f;
#pragma unroll
        for (int j = 0; j < 16; j++) s += F[16 * r + j][d];
        g_xcomp[1][((size_t)b * RWS + r) * DI + dg] = s * (1.f / 16.f);
    }
}

// ---------------- x_proj: 4 r per block ----------------
__global__ void __launch_bounds__(256) xdbl_k(const float* __restrict__ xpw_f,
                                              const float* __restrict__ xpw_b)
{
    __shared__ float xs[4 * DI];
    const int dir = blockIdx.y;
    const int b = blockIdx.x >> 2;
    const int rq = blockIdx.x & 3;

    const float* src = g_xcomp[dir] + ((size_t)b * RWS + rq * 4) * DI;
    for (int i = threadIdx.x; i < 4 * DI; i += 256) xs[i] = src[i];
    __syncthreads();

    const float* xpw = dir ? xpw_b : xpw_f;
    const int warp = threadIdx.x >> 5, lane = threadIdx.x & 31;
    for (int e = warp; e < 80; e += 8) {
        const float* wrow = xpw + (size_t)e * DI;
        float s0 = 0.f, s1 = 0.f, s2 = 0.f, s3 = 0.f;
        for (int k = lane; k < DI; k += 32) {
            const float w = wrow[k];
            s0 += w * xs[k];
            s1 += w * xs[DI + k];
            s2 += w * xs[2 * DI + k];
            s3 += w * xs[3 * DI + k];
        }
#pragma unroll
        for (int off = 16; off >= 1; off >>= 1) {
            s0 += __shfl_xor_sync(0xffffffffu, s0, off);
            s1 += __shfl_xor_sync(0xffffffffu, s1, off);
            s2 += __shfl_xor_sync(0xffffffffu, s2, off);
            s3 += __shfl_xor_sync(0xffffffffu, s3, off);
        }
        if (lane < 4) {
            const float v = (lane == 0) ? s0 : (lane == 1) ? s1 : (lane == 2) ? s2 : s3;
            g_xdbl[dir][((size_t)b * RWS + rq * 4 + lane) * 80 + e] = v;
        }
    }
}

// ---------------- fused dt_proj + softplus + selective scan ----------------
__global__ void __launch_bounds__(128) scan_k(const float* __restrict__ dtw_f,
                                              const float* __restrict__ dtw_b,
                                              const float* __restrict__ dtb_f,
                                              const float* __restrict__ dtb_b,
                                              const float* __restrict__ Alog_f,
                                              const float* __restrict__ Alog_b)
{
    __shared__ float xd[RWS * 80];
    __shared__ float dtws[128][49];

    const int dir = blockIdx.z;
    const int b = blockIdx.y;
    const int d0 = blockIdx.x * 128;
    const int tid = threadIdx.x;
    const int d = d0 + tid;

    const float* xdbl = g_xdbl[dir] + (size_t)b * RWS * 80;
    for (int i = tid; i < RWS * 80; i += 128) xd[i] = xdbl[i];

    const float* dtw = dir ? dtw_b : dtw_f;
    for (int idx = tid; idx < 128 * DTR; idx += 128) {
        const int row = idx / DTR, col = idx % DTR;
        dtws[row][col] = dtw[(size_t)d0 * DTR + idx];
    }
    __syncthreads();

    const float* Alog = (dir ? Alog_b : Alog_f) + (size_t)d * NS;
    const float bias = dir ? dtb_b[d] : dtb_f[d];

    float A[NS];
#pragma unroll
    for (int n = 0; n < NS; n++) A[n] = -expf(Alog[n]);

    const float A0 = A[0];
    bool chain = true;
#pragma unroll
    for (int n = 1; n < NS; n++)
        chain = chain && (fabsf(A[n] - (float)(n + 1) * A0) <= 1e-4f * fabsf(A[n]));

    float u[RWS];
    const float* up = g_xcomp[dir] + (size_t)b * RWS * DI + d;
#pragma unroll
    for (int r = 0; r < RWS; r++) u[r] = up[(size_t)r * DI];

    float h[NS];
#pragma unroll
    for (int n = 0; n < NS; n++) h[n] = 0.f;

    float* yp = g_y[dir] + (size_t)b * RWS * DI + d;
#pragma unroll 1
    for (int r = 0; r < RWS; r++) {
        float dt = bias;
#pragma unroll
        for (int rr = 0; rr < DTR; rr++) dt += xd[r * 80 + rr] * dtws[tid][rr];
        const float delta = fmaxf(dt, 0.f) + log1pf(__expf(-fabsf(dt)));
        const float du = delta * u[r];
        const float qch = __expf(delta * A0);
        float p = 1.f;
        float acc = 0.f;
#pragma unroll
        for (int n = 0; n < NS; n++) {
            float dA;
            if (chain) { p *= qch; dA = p; }
            else       { dA = __expf(delta * A[n]); }
            h[n] = dA * h[n] + du * xd[r * 80 + 48 + n];
            acc += h[n] * xd[r * 80 + 64 + n];
        }
        yp[(size_t)r * DI] = acc;
    }
}

// ---------------- combine + LayerNorm + SiLU(z) gate ----------------
__global__ void __launch_bounds__(256) ln_gate_k(const float* __restrict__ Dp,
                                                 const float* __restrict__ Dpb,
                                                 const float* __restrict__ gamma,
                                                 const float* __restrict__ beta)
{
    const int bl = blockIdx.x;
    const int b = bl >> 8;
    const int l = bl & 255;
    const int lb = 255 - l;
    const int rf = l >> 4, rb = lb >> 4;
    const int tid = threadIdx.x;

    const float* xcf = g_xc[0] + ((size_t)b * LSEQ + l) * DI;
    const float* xcb = g_xc[1] + ((size_t)b * LSEQ + lb) * DI;
    const float* yf = g_y[0] + ((size_t)b * RWS + rf) * DI;
    const float* yb = g_y[1] + ((size_t)b * RWS + rb) * DI;

    float v[6];
    float s = 0.f, s2 = 0.f;
#pragma unroll
    for (int i = 0; i < 6; i++) {
        const int d = tid + i * 256;
        const float cf = yf[d] + Dp[d] * xcf[d];
        const float cbv = yb[d] + Dpb[d] * xcb[d];
        const float val = 0.5f * (cf + cbv);
        v[i] = val;
        s += val;
        s2 += val * val;
    }

    __shared__ float red[16];
#pragma unroll
    for (int off = 16; off >= 1; off >>= 1) {
        s += __shfl_xor_sync(0xffffffffu, s, off);
        s2 += __shfl_xor_sync(0xffffffffu, s2, off);
    }
    const int warp = tid >> 5, lane = tid & 31;
    if (lane == 0) { red[warp] = s; red[warp + 8] = s2; }
    __syncthreads();
    if (warp == 0) {
        float a = (lane < 8) ? red[lane] : 0.f;
        float c = (lane < 8) ? red[lane + 8] : 0.f;
#pragma unroll
        for (int off = 4; off >= 1; off >>= 1) {
            a += __shfl_xor_sync(0xffffffffu, a, off);
            c += __shfl_xor_sync(0xffffffffu, c, off);
        }
        if (lane == 0) { red[0] = a; red[1] = c; }
    }
    __syncthreads();

    const float mean = red[0] * (1.f / DI);
    const float var = red[1] * (1.f / DI) - mean * mean;
    const float rstd = rsqrtf(var + 1e-5f);

#pragma unroll
    for (int i = 0; i < 6; i++) {
        const int d = tid + i * 256;
        const float g = (v[i] - mean) * rstd * gamma[d] + beta[d];
        const float zv = g_z[(size_t)bl * DI + d];
        const float sz = __fdividef(zv, 1.f + __expf(-zv));
        g_gated[(size_t)bl * DI + d] = __float2half_rn(g * sz);
    }
}

// ---------------- launch ----------------
extern "C" void kernel_launch(void* const* d_in, const int* in_sizes, int n_in,
                              void* d_out, int out_size)
{
    const float* hs    = (const float*)d_in[0];
    const float* inw   = (const float*)d_in[1];
    const float* cw    = (const float*)d_in[2];
    const float* cb    = (const float*)d_in[3];
    const float* cwb   = (const float*)d_in[4];
    const float* cbb   = (const float*)d_in[5];
    const float* xpw   = (const float*)d_in[6];
    const float* xpwb  = (const float*)d_in[7];
    const float* dtw   = (const float*)d_in[8];
    const float* dtwb  = (const float*)d_in[9];
    const float* dtb   = (const float*)d_in[10];
    const float* dtbb  = (const float*)d_in[11];
    const float* Alog  = (const float*)d_in[12];
    const float* Alogb = (const float*)d_in[13];
    const float* Dp    = (const float*)d_in[14];
    const float* Dpb   = (const float*)d_in[15];
    const float* gam   = (const float*)d_in[16];
    const float* bet   = (const float*)d_in[17];
    const float* opw   = (const float*)d_in[18];
    float* out = (float*)d_out;

    // 1) in_proj: (16384 x 768) x (3072 x 768)^T -> g_x | g_z
    mma_gemm<1><<<dim3(3072 / 128, 16384 / 256), 512>>>(hs, inw, nullptr, DM);
    // 2) depthwise conv + SiLU + block means (both directions)
    conv_silu_k<<<dim3(DI / 16, B_SZ), 256>>>(cw, cb, cwb, cbb);
    // 3) x_proj
    xdbl_k<<<dim3(B_SZ * 4, 2), 256>>>(xpw, xpwb);
    // 4) dt_proj + selective scan
    scan_k<<<dim3(DI / 128, B_SZ, 2), 128>>>(dtw, dtwb, dtb, dtbb, Alog, Alogb);
    // 5) combine + LN + gate (writes half g_gated)
    ln_gate_k<<<B_SZ * LSEQ, 256>>>(Dp, Dpb, gam, bet);
    // 6) out_proj: (16384 x 1536) x (768 x 1536)^T -> d_out
    mma_gemm<2><<<dim3(768 / 128, 16384 / 256), 512>>>(nullptr, opw, out, DI);
}

// round 11
// speedup vs baseline: 7.3153x; 1.2755x over previous
#include <cuda_runtime.h>
#include <cuda_fp16.h>
#include <math.h>
#include <stdint.h>

#define B_SZ  64
#define DM    768
#define DI    1536
#define NS    16
#define LSEQ  256
#define RWS   16
#define DTR   48

// ---------------- scratch (static device arrays; no allocation) ----------------
__device__ float  g_x[B_SZ * LSEQ * DI];          // (b, l, d)
__device__ __half g_zh[B_SZ * LSEQ * DI];         // (b, l, d) half
__device__ __half g_xch[2][B_SZ * LSEQ * DI];     // conv+silu, half
__device__ float  g_xcomp[2][B_SZ * RWS * DI];    // (b, r, d)
__device__ float  g_xdbl[2][B_SZ * RWS * 80];     // (b, r, e)
__device__ float  g_y[2][B_SZ * RWS * DI];        // (b, r, d)
__device__ __half g_gated[B_SZ * LSEQ * DI];      // (b*l, d) half
__device__ __half g_hsh[B_SZ * LSEQ * DM];        // hidden_states half
__device__ __half g_wih[2 * DI * DM];             // in_proj_w half
__device__ __half g_woh[DM * DI];                 // out_proj_w half

// ---------------- helpers ----------------
__device__ __forceinline__ void mma_f16(float* c, const unsigned* a, const unsigned* b) {
    asm volatile(
        "mma.sync.aligned.m16n8k16.row.col.f32.f16.f16.f32 "
        "{%0,%1,%2,%3}, {%4,%5,%6,%7}, {%8,%9}, {%0,%1,%2,%3};"
        : "+f"(c[0]), "+f"(c[1]), "+f"(c[2]), "+f"(c[3])
        : "r"(a[0]), "r"(a[1]), "r"(a[2]), "r"(a[3]), "r"(b[0]), "r"(b[1]));
}
__device__ __forceinline__ unsigned pack_half2(float x, float y) {
    __half2 h = __floats2half2_rn(x, y);
    return *(unsigned*)&h;
}
__device__ __forceinline__ void cp16(uint32_t dst, const void* src) {
    asm volatile("cp.async.cg.shared.global [%0], [%1], 16;" :: "r"(dst), "l"(src));
}
#define CP_COMMIT() asm volatile("cp.async.commit_group;" ::: "memory")
#define CP_WAIT0()  asm volatile("cp.async.wait_group 0;" ::: "memory")

// ---------------- fp32 -> fp16 convert (vectorized) ----------------
__global__ void __launch_bounds__(256) f2h_k(const float* __restrict__ src,
                                             __half* __restrict__ dst, int n4)
{
    const int i = blockIdx.x * 256 + threadIdx.x;
    if (i < n4) {
        float4 v = ((const float4*)src)[i];
        uint2 o;
        o.x = pack_half2(v.x, v.y);
        o.y = pack_half2(v.z, v.w);
        ((uint2*)dst)[i] = o;
    }
}

// ---------------- fp16 GEMM (cp.async double-buffered): C[m,n] = sum_k A[m,k]*W[n,k] ----------------
// Block 128x128, BK=32, 256 threads = 8 warps (2m x 4n), warp tile 64x32.
// MODE 1: A=g_hsh, W=g_wih; split epilogue -> g_x (f32) / g_zh (half)  (K=768,  N=3072)
// MODE 2: A=g_gated, W=g_woh; C=out f32                                 (K=1536, N=768)
template<int MODE>
__global__ void __launch_bounds__(256, 2) hgemm(float* __restrict__ C, int K)
{
    __shared__ __half As[2][128][40];
    __shared__ __half Bs[2][128][40];

    const __half* Ah = (MODE == 1) ? (const __half*)g_hsh : (const __half*)g_gated;
    const __half* Wh = (MODE == 1) ? (const __half*)g_wih : (const __half*)g_woh;

    const int tid = threadIdx.x;
    const int warp = tid >> 5, lane = tid & 31;
    const int m0 = blockIdx.y * 128, n0 = blockIdx.x * 128;
    const int wm = (warp >> 2) * 64;       // 0 or 64
    const int wn = (warp & 3) * 32;        // 0..96
    const int grp = lane >> 2, tig = lane & 3;

    // load mapping: 4 cp.async/thread/stage (A row, A row+64, B row, B row+64)
    const int lchunk = tid & 3;            // 16B chunk within 64B row (8 halves)
    const int lrow = tid >> 2;             // 0..63

    const __half* Abase = Ah + (size_t)(m0 + lrow) * K + lchunk * 8;
    const __half* Bbase = Wh + (size_t)(n0 + lrow) * K + lchunk * 8;
    const size_t row64 = (size_t)64 * K;

    uint32_t asd[2][2], bsd[2][2];
#pragma unroll
    for (int s = 0; s < 2; s++) {
        asd[s][0] = (uint32_t)__cvta_generic_to_shared(&As[s][lrow][lchunk * 8]);
        asd[s][1] = (uint32_t)__cvta_generic_to_shared(&As[s][lrow + 64][lchunk * 8]);
        bsd[s][0] = (uint32_t)__cvta_generic_to_shared(&Bs[s][lrow][lchunk * 8]);
        bsd[s][1] = (uint32_t)__cvta_generic_to_shared(&Bs[s][lrow + 64][lchunk * 8]);
    }

    float acc[4][4][4];
#pragma unroll
    for (int i = 0; i < 4; i++)
#pragma unroll
        for (int j = 0; j < 4; j++)
#pragma unroll
            for (int r = 0; r < 4; r++) acc[i][j][r] = 0.f;

    const int NIT = K / 32;

    // prologue: stage 0
    cp16(asd[0][0], Abase);
    cp16(asd[0][1], Abase + row64);
    cp16(bsd[0][0], Bbase);
    cp16(bsd[0][1], Bbase + row64);
    CP_COMMIT();

    for (int it = 0; it < NIT; ++it) {
        CP_WAIT0();
        __syncthreads();

        // issue next stage (safe: barrier above guarantees compute(it-1) done)
        if (it + 1 < NIT) {
            const int nxt = (it + 1) & 1;
            const int k0 = (it + 1) * 32;
            cp16(asd[nxt][0], Abase + k0);
            cp16(asd[nxt][1], Abase + row64 + k0);
            cp16(bsd[nxt][0], Bbase + k0);
            cp16(bsd[nxt][1], Bbase + row64 + k0);
            CP_COMMIT();
        }

        const int s = it & 1;
#pragma unroll
        for (int ks = 0; ks < 2; ks++) {
            const int kc = ks * 16;
            unsigned afr[4][4], bfr[4][2];
#pragma unroll
            for (int mt = 0; mt < 4; mt++) {
                const int rb = wm + mt * 16 + grp;
                afr[mt][0] = *(const unsigned*)&As[s][rb][kc + 2 * tig];
                afr[mt][1] = *(const unsigned*)&As[s][rb + 8][kc + 2 * tig];
                afr[mt][2] = *(const unsigned*)&As[s][rb][kc + 2 * tig + 8];
                afr[mt][3] = *(const unsigned*)&As[s][rb + 8][kc + 2 * tig + 8];
            }
#pragma unroll
            for (int nt = 0; nt < 4; nt++) {
                const int nb = wn + nt * 8 + grp;
                bfr[nt][0] = *(const unsigned*)&Bs[s][nb][kc + 2 * tig];
                bfr[nt][1] = *(const unsigned*)&Bs[s][nb][kc + 2 * tig + 8];
            }
#pragma unroll
            for (int mt = 0; mt < 4; mt++)
#pragma unroll
                for (int nt = 0; nt < 4; nt++)
                    mma_f16(acc[mt][nt], afr[mt], bfr[nt]);
        }
    }

    // epilogue
#pragma unroll
    for (int mt = 0; mt < 4; mt++) {
#pragma unroll
        for (int nt = 0; nt < 4; nt++) {
            const int m = m0 + wm + mt * 16 + grp;
            const int n = n0 + wn + nt * 8 + 2 * tig;
            if (MODE == 1) {
                if (n0 < DI) {
                    *(float2*)&g_x[(size_t)m * DI + n] = make_float2(acc[mt][nt][0], acc[mt][nt][1]);
                    *(float2*)&g_x[(size_t)(m + 8) * DI + n] = make_float2(acc[mt][nt][2], acc[mt][nt][3]);
                } else {
                    const int nn = n - DI;
                    *(unsigned*)&g_zh[(size_t)m * DI + nn] = pack_half2(acc[mt][nt][0], acc[mt][nt][1]);
                    *(unsigned*)&g_zh[(size_t)(m + 8) * DI + nn] = pack_half2(acc[mt][nt][2], acc[mt][nt][3]);
                }
            } else {
                *(float2*)&C[(size_t)m * 768 + n] = make_float2(acc[mt][nt][0], acc[mt][nt][1]);
                *(float2*)&C[(size_t)(m + 8) * 768 + n] = make_float2(acc[mt][nt][2], acc[mt][nt][3]);
            }
        }
    }
}

// ---------------- conv + SiLU + 16-block mean (both directions, tiled) ----------------
__global__ void __launch_bounds__(256) conv_silu_k(const float* __restrict__ cw,
                                                   const float* __restrict__ cb,
                                                   const float* __restrict__ cwb,
                                                   const float* __restrict__ cbb)
{
    __shared__ float X[256][17];
    __shared__ float F[256][17];

    const int d0 = blockIdx.x * 16;
    const int b = blockIdx.y;
    const int tid = threadIdx.x;

#pragma unroll
    for (int i = 0; i < 4; i++) {
        const int idx = tid + 256 * i;
        const int l = idx >> 2, q = idx & 3;
        float4 v = *(const float4*)&g_x[((size_t)b * LSEQ + l) * DI + d0 + 4 * q];
        X[l][4 * q + 0] = v.x; X[l][4 * q + 1] = v.y;
        X[l][4 * q + 2] = v.z; X[l][4 * q + 3] = v.w;
    }
    __syncthreads();

    const int sub = tid >> 4;
    const int d = tid & 15;
    const int dg = d0 + d;

    {
        float w[4];
#pragma unroll
        for (int k = 0; k < 4; k++) w[k] = cw[dg * 4 + k];
        const float bias = cb[dg];
#pragma unroll
        for (int i = 0; i < 16; i++) {
            const int l = i * 16 + sub;
            float a = bias;
#pragma unroll
            for (int k = 0; k < 4; k++) {
                const int idx = l - 3 + k;
                if (idx >= 0) a += w[k] * X[idx][d];
            }
            const float s = __fdividef(a, 1.f + __expf(-a));
            F[l][d] = s;
            g_xch[0][((size_t)b * LSEQ + l) * DI + dg] = __float2half_rn(s);
        }
    }
    __syncthreads();
    {
        const int r = tid >> 4;
        float s = 0.f;
#pragma unroll
        for (int j = 0; j < 16; j++) s += F[16 * r + j][d];
        g_xcomp[0][((size_t)b * RWS + r) * DI + dg] = s * (1.f / 16.f);
    }
    __syncthreads();

    {
        float w[4];
#pragma unroll
        for (int k = 0; k < 4; k++) w[k] = cwb[dg * 4 + k];
        const float bias = cbb[dg];
#pragma unroll
        for (int i = 0; i < 16; i++) {
            const int l = i * 16 + sub;
            float a = bias;
#pragma unroll
            for (int k = 0; k < 4; k++) {
                const int idx = l - 3 + k;
                if (idx >= 0) a += w[k] * X[255 - idx][d];
            }
            const float s = __fdividef(a, 1.f + __expf(-a));
            F[l][d] = s;
            g_xch[1][((size_t)b * LSEQ + l) * DI + dg] = __float2half_rn(s);
        }
    }
    __syncthreads();
    {
        const int r = tid >> 4;
        float s = 0.f;
#pragma unroll
        for (int j = 0; j < 16; j++) s += F[16 * r + j][d];
        g_xcomp[1][((size_t)b * RWS + r) * DI + dg] = s * (1.f / 16.f);
    }
}

// ---------------- x_proj: 4 r per block ----------------
__global__ void __launch_bounds__(256) xdbl_k(const float* __restrict__ xpw_f,
                                              const float* __restrict__ xpw_b)
{
    __shared__ float xs[4 * DI];
    const int dir = blockIdx.y;
    const int b = blockIdx.x >> 2;
    const int rq = blockIdx.x & 3;

    const float* src = g_xcomp[dir] + ((size_t)b * RWS + rq * 4) * DI;
    for (int i = threadIdx.x; i < 4 * DI; i += 256) xs[i] = src[i];
    __syncthreads();

    const float* xpw = dir ? xpw_b : xpw_f;
    const int warp = threadIdx.x >> 5, lane = threadIdx.x & 31;
    for (int e = warp; e < 80; e += 8) {
        const float* wrow = xpw + (size_t)e * DI;
        float s0 = 0.f, s1 = 0.f, s2 = 0.f, s3 = 0.f;
        for (int k = lane; k < DI; k += 32) {
            const float w = wrow[k];
            s0 += w * xs[k];
            s1 += w * xs[DI + k];
            s2 += w * xs[2 * DI + k];
            s3 += w * xs[3 * DI + k];
        }
#pragma unroll
        for (int off = 16; off >= 1; off >>= 1) {
            s0 += __shfl_xor_sync(0xffffffffu, s0, off);
            s1 += __shfl_xor_sync(0xffffffffu, s1, off);
            s2 += __shfl_xor_sync(0xffffffffu, s2, off);
            s3 += __shfl_xor_sync(0xffffffffu, s3, off);
        }
        if (lane < 4) {
            const float v = (lane == 0) ? s0 : (lane == 1) ? s1 : (lane == 2) ? s2 : s3;
            g_xdbl[dir][((size_t)b * RWS + rq * 4 + lane) * 80 + e] = v;
        }
    }
}

// ---------------- fused dt_proj + softplus + selective scan ----------------
__global__ void __launch_bounds__(128) scan_k(const float* __restrict__ dtw_f,
                                              const float* __restrict__ dtw_b,
                                              const float* __restrict__ dtb_f,
                                              const float* __restrict__ dtb_b,
                                              const float* __restrict__ Alog_f,
                                              const float* __restrict__ Alog_b)
{
    __shared__ float xd[RWS * 80];
    __shared__ float dtws[128][49];

    const int dir = blockIdx.z;
    const int b = blockIdx.y;
    const int d0 = blockIdx.x * 128;
    const int tid = threadIdx.x;
    const int d = d0 + tid;

    const float* xdbl = g_xdbl[dir] + (size_t)b * RWS * 80;
    for (int i = tid; i < RWS * 80; i += 128) xd[i] = xdbl[i];

    const float* dtw = dir ? dtw_b : dtw_f;
    for (int idx = tid; idx < 128 * DTR; idx += 128) {
        const int row = idx / DTR, col = idx % DTR;
        dtws[row][col] = dtw[(size_t)d0 * DTR + idx];
    }
    __syncthreads();

    const float* Alog = (dir ? Alog_b : Alog_f) + (size_t)d * NS;
    const float bias = dir ? dtb_b[d] : dtb_f[d];

    float A[NS];
#pragma unroll
    for (int n = 0; n < NS; n++) A[n] = -expf(Alog[n]);

    const float A0 = A[0];
    bool chain = true;
#pragma unroll
    for (int n = 1; n < NS; n++)
        chain = chain && (fabsf(A[n] - (float)(n + 1) * A0) <= 1e-4f * fabsf(A[n]));

    float u[RWS];
    const float* up = g_xcomp[dir] + (size_t)b * RWS * DI + d;
#pragma unroll
    for (int r = 0; r < RWS; r++) u[r] = up[(size_t)r * DI];

    float h[NS];
#pragma unroll
    for (int n = 0; n < NS; n++) h[n] = 0.f;

    float* yp = g_y[dir] + (size_t)b * RWS * DI + d;
#pragma unroll 1
    for (int r = 0; r < RWS; r++) {
        float dt = bias;
#pragma unroll
        for (int rr = 0; rr < DTR; rr++) dt += xd[r * 80 + rr] * dtws[tid][rr];
        const float delta = fmaxf(dt, 0.f) + log1pf(__expf(-fabsf(dt)));
        const float du = delta * u[r];
        const float qch = __expf(delta * A0);
        float p = 1.f;
        float acc = 0.f;
#pragma unroll
        for (int n = 0; n < NS; n++) {
            float dA;
            if (chain) { p *= qch; dA = p; }
            else       { dA = __expf(delta * A[n]); }
            h[n] = dA * h[n] + du * xd[r * 80 + 48 + n];
            acc += h[n] * xd[r * 80 + 64 + n];
        }
        yp[(size_t)r * DI] = acc;
    }
}

// ---------------- combine + LayerNorm + SiLU(z) gate ----------------
__global__ void __launch_bounds__(256) ln_gate_k(const float* __restrict__ Dp,
                                                 const float* __restrict__ Dpb,
                                                 const float* __restrict__ gamma,
                                                 const float* __restrict__ beta)
{
    const int bl = blockIdx.x;
    const int b = bl >> 8;
    const int l = bl & 255;
    const int lb = 255 - l;
    const int rf = l >> 4, rb = lb >> 4;
    const int tid = threadIdx.x;

    const __half* xcf = g_xch[0] + ((size_t)b * LSEQ + l) * DI;
    const __half* xcb = g_xch[1] + ((size_t)b * LSEQ + lb) * DI;
    const float* yf = g_y[0] + ((size_t)b * RWS + rf) * DI;
    const float* yb = g_y[1] + ((size_t)b * RWS + rb) * DI;

    float v[6];
    float s = 0.f, s2 = 0.f;
#pragma unroll
    for (int i = 0; i < 6; i++) {
        const int d = tid + i * 256;
        const float cf = yf[d] + Dp[d] * __half2float(xcf[d]);
        const float cbv = yb[d] + Dpb[d] * __half2float(xcb[d]);
        const float val = 0.5f * (cf + cbv);
        v[i] = val;
        s += val;
        s2 += val * val;
    }

    __shared__ float red[16];
#pragma unroll
    for (int off = 16; off >= 1; off >>= 1) {
        s += __shfl_xor_sync(0xffffffffu, s, off);
        s2 += __shfl_xor_sync(0xffffffffu, s2, off);
    }
    const int warp = tid >> 5, lane = tid & 31;
    if (lane == 0) { red[warp] = s; red[warp + 8] = s2; }
    __syncthreads();
    if (warp == 0) {
        float a = (lane < 8) ? red[lane] : 0.f;
        float c = (lane < 8) ? red[lane + 8] : 0.f;
#pragma unroll
        for (int off = 4; off >= 1; off >>= 1) {
            a += __shfl_xor_sync(0xffffffffu, a, off);
            c += __shfl_xor_sync(0xffffffffu, c, off);
        }
        if (lane == 0) { red[0] = a; red[1] = c; }
    }
    __syncthreads();

    const float mean = red[0] * (1.f / DI);
    const float var = red[1] * (1.f / DI) - mean * mean;
    const float rstd = rsqrtf(var + 1e-5f);

#pragma unroll
    for (int i = 0; i < 6; i++) {
        const int d = tid + i * 256;
        const float g = (v[i] - mean) * rstd * gamma[d] + beta[d];
        const float zv = __half2float(g_zh[(size_t)bl * DI + d]);
        const float sz = __fdividef(zv, 1.f + __expf(-zv));
        g_gated[(size_t)bl * DI + d] = __float2half_rn(g * sz);
    }
}

// ---------------- launch ----------------
extern "C" void kernel_launch(void* const* d_in, const int* in_sizes, int n_in,
                              void* d_out, int out_size)
{
    const float* hs    = (const float*)d_in[0];
    const float* inw   = (const float*)d_in[1];
    const float* cw    = (const float*)d_in[2];
    const float* cb    = (const float*)d_in[3];
    const float* cwb   = (const float*)d_in[4];
    const float* cbb   = (const float*)d_in[5];
    const float* xpw   = (const float*)d_in[6];
    const float* xpwb  = (const float*)d_in[7];
    const float* dtw   = (const float*)d_in[8];
    const float* dtwb  = (const float*)d_in[9];
    const float* dtb   = (const float*)d_in[10];
    const float* dtbb  = (const float*)d_in[11];
    const float* Alog  = (const float*)d_in[12];
    const float* Alogb = (const float*)d_in[13];
    const float* Dp    = (const float*)d_in[14];
    const float* Dpb   = (const float*)d_in[15];
    const float* gam   = (const float*)d_in[16];
    const float* bet   = (const float*)d_in[17];
    const float* opw   = (const float*)d_in[18];
    float* out = (float*)d_out;

    __half *d_hsh, *d_wih, *d_woh;
    cudaGetSymbolAddress((void**)&d_hsh, g_hsh);
    cudaGetSymbolAddress((void**)&d_wih, g_wih);
    cudaGetSymbolAddress((void**)&d_woh, g_woh);

    // 0) convert fp32 inputs to half
    {
        const int n1 = B_SZ * LSEQ * DM / 4;      // hs
        const int n2 = 2 * DI * DM / 4;           // in_proj_w
        const int n3 = DM * DI / 4;               // out_proj_w
        f2h_k<<<(n1 + 255) / 256, 256>>>(hs, d_hsh, n1);
        f2h_k<<<(n2 + 255) / 256, 256>>>(inw, d_wih, n2);
        f2h_k<<<(n3 + 255) / 256, 256>>>(opw, d_woh, n3);
    }
    // 1) in_proj: (16384 x 768) x (3072 x 768)^T -> g_x | g_zh
    hgemm<1><<<dim3(3072 / 128, 16384 / 128), 256>>>(nullptr, DM);
    // 2) depthwise conv + SiLU + block means
    conv_silu_k<<<dim3(DI / 16, B_SZ), 256>>>(cw, cb, cwb, cbb);
    // 3) x_proj
    xdbl_k<<<dim3(B_SZ * 4, 2), 256>>>(xpw, xpwb);
    // 4) dt_proj + selective scan
    scan_k<<<dim3(DI / 128, B_SZ, 2), 128>>>(dtw, dtwb, dtb, dtbb, Alog, Alogb);
    // 5) combine + LN + gate
    ln_gate_k<<<B_SZ * LSEQ, 256>>>(Dp, Dpb, gam, bet);
    // 6) out_proj: (16384 x 1536) x (768 x 1536)^T -> d_out
    hgemm<2><<<dim3(768 / 128, 16384 / 128), 256>>>(out, DI);
}

// round 14
// speedup vs baseline: 7.4002x; 1.0116x over previous
#include <cuda_runtime.h>
#include <cuda_fp16.h>
#include <math.h>
#include <stdint.h>

#define B_SZ  64
#define DM    768
#define DI    1536
#define NS    16
#define LSEQ  256
#define RWS   16
#define DTR   48

// ---------------- scratch (static device arrays; no allocation) ----------------
__device__ float  g_x[B_SZ * LSEQ * DI];          // (b, l, d)
__device__ __half g_zh[B_SZ * LSEQ * DI];         // (b, l, d) half
__device__ __half g_xch[2][B_SZ * LSEQ * DI];     // conv+silu, half
__device__ float  g_xcomp[2][B_SZ * RWS * DI];    // (b, r, d)
__device__ float  g_xdbl[2][B_SZ * RWS * 80];     // (b, r, e)
__device__ float  g_y[2][B_SZ * RWS * DI];        // (b, r, d)
__device__ __half g_gated[B_SZ * LSEQ * DI];      // (b*l, d) half
__device__ __half g_hsh[B_SZ * LSEQ * DM];        // hidden_states half
__device__ __half g_wih[2 * DI * DM];             // in_proj_w half
__device__ __half g_woh[DM * DI];                 // out_proj_w half

// ---------------- helpers ----------------
__device__ __forceinline__ void mma_f16(float* c, const unsigned* a, const unsigned* b) {
    asm volatile(
        "mma.sync.aligned.m16n8k16.row.col.f32.f16.f16.f32 "
        "{%0,%1,%2,%3}, {%4,%5,%6,%7}, {%8,%9}, {%0,%1,%2,%3};"
        : "+f"(c[0]), "+f"(c[1]), "+f"(c[2]), "+f"(c[3])
        : "r"(a[0]), "r"(a[1]), "r"(a[2]), "r"(a[3]), "r"(b[0]), "r"(b[1]));
}
__device__ __forceinline__ unsigned pack_half2(float x, float y) {
    __half2 h = __floats2half2_rn(x, y);
    return *(unsigned*)&h;
}
__device__ __forceinline__ void cp16(uint32_t dst, const void* src) {
    asm volatile("cp.async.cg.shared.global [%0], [%1], 16;" :: "r"(dst), "l"(src));
}
#define CP_COMMIT() asm volatile("cp.async.commit_group;" ::: "memory")
#define CP_WAIT1()  asm volatile("cp.async.wait_group 1;" ::: "memory")
#define CP_WAIT0()  asm volatile("cp.async.wait_group 0;" ::: "memory")

// ---------------- fp32 -> fp16 convert (vectorized) ----------------
__global__ void __launch_bounds__(256) f2h_k(const float* __restrict__ src,
                                             __half* __restrict__ dst, int n4)
{
    const int i = blockIdx.x * 256 + threadIdx.x;
    if (i < n4) {
        float4 v = ((const float4*)src)[i];
        uint2 o;
        o.x = pack_half2(v.x, v.y);
        o.y = pack_half2(v.z, v.w);
        ((uint2*)dst)[i] = o;
    }
}

// ---------------- fp16 GEMM (3-stage cp.async): C[m,n] = sum_k A[m,k]*W[n,k] ----------------
// Block 128x128, BK=32, 256 threads = 8 warps (2m x 4n), warp tile 64x32. 3 smem stages.
// MODE 1: A=g_hsh, W=g_wih; split epilogue -> g_x (f32) / g_zh (half)  (K=768,  N=3072)
// MODE 2: A=g_gated, W=g_woh; C=out f32                                 (K=1536, N=768)
#define HG_STAGES 3
#define HG_STAGE_HALVES (128 * 40)
#define HG_SMEM_BYTES (HG_STAGES * 2 * HG_STAGE_HALVES * 2)

template<int MODE>
__global__ void __launch_bounds__(256, 2) hgemm(float* __restrict__ C, int K)
{
    extern __shared__ __half sm[];
    // layout: A stages [0..2], then B stages [0..2]
    __half* Asm = sm;
    __half* Bsm = sm + HG_STAGES * HG_STAGE_HALVES;

    const __half* Ah = (MODE == 1) ? (const __half*)g_hsh : (const __half*)g_gated;
    const __half* Wh = (MODE == 1) ? (const __half*)g_wih : (const __half*)g_woh;

    const int tid = threadIdx.x;
    const int warp = tid >> 5, lane = tid & 31;
    const int m0 = blockIdx.y * 128, n0 = blockIdx.x * 128;
    const int wm = (warp >> 2) * 64;       // 0 or 64
    const int wn = (warp & 3) * 32;        // 0..96
    const int grp = lane >> 2, tig = lane & 3;

    // load mapping: 4 cp.async/thread/stage (A row, A row+64, B row, B row+64)
    const int lchunk = tid & 3;            // 16B chunk (8 halves) within 64-half row
    const int lrow = tid >> 2;             // 0..63

    const __half* Abase = Ah + (size_t)(m0 + lrow) * K + lchunk * 8;
    const __half* Bbase = Wh + (size_t)(n0 + lrow) * K + lchunk * 8;
    const size_t row64 = (size_t)64 * K;

    uint32_t asd[HG_STAGES][2], bsd[HG_STAGES][2];
#pragma unroll
    for (int s = 0; s < HG_STAGES; s++) {
        asd[s][0] = (uint32_t)__cvta_generic_to_shared(Asm + s * HG_STAGE_HALVES + lrow * 40 + lchunk * 8);
        asd[s][1] = (uint32_t)__cvta_generic_to_shared(Asm + s * HG_STAGE_HALVES + (lrow + 64) * 40 + lchunk * 8);
        bsd[s][0] = (uint32_t)__cvta_generic_to_shared(Bsm + s * HG_STAGE_HALVES + lrow * 40 + lchunk * 8);
        bsd[s][1] = (uint32_t)__cvta_generic_to_shared(Bsm + s * HG_STAGE_HALVES + (lrow + 64) * 40 + lchunk * 8);
    }

    float acc[4][4][4];
#pragma unroll
    for (int i = 0; i < 4; i++)
#pragma unroll
        for (int j = 0; j < 4; j++)
#pragma unroll
            for (int r = 0; r < 4; r++) acc[i][j][r] = 0.f;

    const int NIT = K / 32;

    // prologue: stages 0 and 1
#pragma unroll
    for (int s = 0; s < 2; s++) {
        const int k0 = s * 32;
        cp16(asd[s][0], Abase + k0);
        cp16(asd[s][1], Abase + row64 + k0);
        cp16(bsd[s][0], Bbase + k0);
        cp16(bsd[s][1], Bbase + row64 + k0);
        CP_COMMIT();
    }

    int st = 0;
    for (int it = 0; it < NIT; ++it) {
        if (it + 2 < NIT) CP_WAIT1();
        else              CP_WAIT0();
        __syncthreads();

        // issue stage it+2 (its buffer was consumed in iteration it-1; barrier above orders it)
        if (it + 2 < NIT) {
            const int ns = (st + 2 >= HG_STAGES) ? st + 2 - HG_STAGES : st + 2;
            const int k0 = (it + 2) * 32;
            cp16(asd[ns][0], Abase + k0);
            cp16(asd[ns][1], Abase + row64 + k0);
            cp16(bsd[ns][0], Bbase + k0);
            cp16(bsd[ns][1], Bbase + row64 + k0);
            CP_COMMIT();
        }

        const __half* Ast = Asm + st * HG_STAGE_HALVES;
        const __half* Bst = Bsm + st * HG_STAGE_HALVES;
#pragma unroll
        for (int ks = 0; ks < 2; ks++) {
            const int kc = ks * 16;
            unsigned afr[4][4], bfr[4][2];
#pragma unroll
            for (int mt = 0; mt < 4; mt++) {
                const int rb = wm + mt * 16 + grp;
                afr[mt][0] = *(const unsigned*)&Ast[rb * 40 + kc + 2 * tig];
                afr[mt][1] = *(const unsigned*)&Ast[(rb + 8) * 40 + kc + 2 * tig];
                afr[mt][2] = *(const unsigned*)&Ast[rb * 40 + kc + 2 * tig + 8];
                afr[mt][3] = *(const unsigned*)&Ast[(rb + 8) * 40 + kc + 2 * tig + 8];
            }
#pragma unroll
            for (int nt = 0; nt < 4; nt++) {
                const int nb = wn + nt * 8 + grp;
                bfr[nt][0] = *(const unsigned*)&Bst[nb * 40 + kc + 2 * tig];
                bfr[nt][1] = *(const unsigned*)&Bst[nb * 40 + kc + 2 * tig + 8];
            }
#pragma unroll
            for (int mt = 0; mt < 4; mt++)
#pragma unroll
                for (int nt = 0; nt < 4; nt++)
                    mma_f16(acc[mt][nt], afr[mt], bfr[nt]);
        }
        st = (st + 1 >= HG_STAGES) ? 0 : st + 1;
    }

    // epilogue
#pragma unroll
    for (int mt = 0; mt < 4; mt++) {
#pragma unroll
        for (int nt = 0; nt < 4; nt++) {
            const int m = m0 + wm + mt * 16 + grp;
            const int n = n0 + wn + nt * 8 + 2 * tig;
            if (MODE == 1) {
                if (n0 < DI) {
                    *(float2*)&g_x[(size_t)m * DI + n] = make_float2(acc[mt][nt][0], acc[mt][nt][1]);
                    *(float2*)&g_x[(size_t)(m + 8) * DI + n] = make_float2(acc[mt][nt][2], acc[mt][nt][3]);
                } else {
                    const int nn = n - DI;
                    *(unsigned*)&g_zh[(size_t)m * DI + nn] = pack_half2(acc[mt][nt][0], acc[mt][nt][1]);
                    *(unsigned*)&g_zh[(size_t)(m + 8) * DI + nn] = pack_half2(acc[mt][nt][2], acc[mt][nt][3]);
                }
            } else {
                *(float2*)&C[(size_t)m * 768 + n] = make_float2(acc[mt][nt][0], acc[mt][nt][1]);
                *(float2*)&C[(size_t)(m + 8) * 768 + n] = make_float2(acc[mt][nt][2], acc[mt][nt][3]);
            }
        }
    }
}

// ---------------- conv + SiLU + 16-block mean (both directions, tiled) ----------------
__global__ void __launch_bounds__(256) conv_silu_k(const float* __restrict__ cw,
                                                   const float* __restrict__ cb,
                                                   const float* __restrict__ cwb,
                                                   const float* __restrict__ cbb)
{
    __shared__ float X[256][17];
    __shared__ float F[256][17];

    const int d0 = blockIdx.x * 16;
    const int b = blockIdx.y;
    const int tid = threadIdx.x;

#pragma unroll
    for (int i = 0; i < 4; i++) {
        const int idx = tid + 256 * i;
        const int l = idx >> 2, q = idx & 3;
        float4 v = *(const float4*)&g_x[((size_t)b * LSEQ + l) * DI + d0 + 4 * q];
        X[l][4 * q + 0] = v.x; X[l][4 * q + 1] = v.y;
        X[l][4 * q + 2] = v.z; X[l][4 * q + 3] = v.w;
    }
    __syncthreads();

    const int sub = tid >> 4;
    const int d = tid & 15;
    const int dg = d0 + d;

    {
        float w[4];
#pragma unroll
        for (int k = 0; k < 4; k++) w[k] = cw[dg * 4 + k];
        const float bias = cb[dg];
#pragma unroll
        for (int i = 0; i < 16; i++) {
            const int l = i * 16 + sub;
            float a = bias;
#pragma unroll
            for (int k = 0; k < 4; k++) {
                const int idx = l - 3 + k;
                if (idx >= 0) a += w[k] * X[idx][d];
            }
            const float s = __fdividef(a, 1.f + __expf(-a));
            F[l][d] = s;
            g_xch[0][((size_t)b * LSEQ + l) * DI + dg] = __float2half_rn(s);
        }
    }
    __syncthreads();
    {
        const int r = tid >> 4;
        float s = 0.f;
#pragma unroll
        for (int j = 0; j < 16; j++) s += F[16 * r + j][d];
        g_xcomp[0][((size_t)b * RWS + r) * DI + dg] = s * (1.f / 16.f);
    }
    __syncthreads();

    {
        float w[4];
#pragma unroll
        for (int k = 0; k < 4; k++) w[k] = cwb[dg * 4 + k];
        const float bias = cbb[dg];
#pragma unroll
        for (int i = 0; i < 16; i++) {
            const int l = i * 16 + sub;
            float a = bias;
#pragma unroll
            for (int k = 0; k < 4; k++) {
                const int idx = l - 3 + k;
                if (idx >= 0) a += w[k] * X[255 - idx][d];
            }
            const float s = __fdividef(a, 1.f + __expf(-a));
            F[l][d] = s;
            g_xch[1][((size_t)b * LSEQ + l) * DI + dg] = __float2half_rn(s);
        }
    }
    __syncthreads();
    {
        const int r = tid >> 4;
        float s = 0.f;
#pragma unroll
        for (int j = 0; j < 16; j++) s += F[16 * r + j][d];
        g_xcomp[1][((size_t)b * RWS + r) * DI + dg] = s * (1.f / 16.f);
    }
}

// ---------------- x_proj: 4 r per block ----------------
__global__ void __launch_bounds__(256) xdbl_k(const float* __restrict__ xpw_f,
                                              const float* __restrict__ xpw_b)
{
    __shared__ float xs[4 * DI];
    const int dir = blockIdx.y;
    const int b = blockIdx.x >> 2;
    const int rq = blockIdx.x & 3;

    const float* src = g_xcomp[dir] + ((size_t)b * RWS + rq * 4) * DI;
    for (int i = threadIdx.x; i < 4 * DI; i += 256) xs[i] = src[i];
    __syncthreads();

    const float* xpw = dir ? xpw_b : xpw_f;
    const int warp = threadIdx.x >> 5, lane = threadIdx.x & 31;
    for (int e = warp; e < 80; e += 8) {
        const float* wrow = xpw + (size_t)e * DI;
        float s0 = 0.f, s1 = 0.f, s2 = 0.f, s3 = 0.f;
        for (int k = lane; k < DI; k += 32) {
            const float w = wrow[k];
            s0 += w * xs[k];
            s1 += w * xs[DI + k];
            s2 += w * xs[2 * DI + k];
            s3 += w * xs[3 * DI + k];
        }
#pragma unroll
        for (int off = 16; off >= 1; off >>= 1) {
            s0 += __shfl_xor_sync(0xffffffffu, s0, off);
            s1 += __shfl_xor_sync(0xffffffffu, s1, off);
            s2 += __shfl_xor_sync(0xffffffffu, s2, off);
            s3 += __shfl_xor_sync(0xffffffffu, s3, off);
        }
        if (lane < 4) {
            const float v = (lane == 0) ? s0 : (lane == 1) ? s1 : (lane == 2) ? s2 : s3;
            g_xdbl[dir][((size_t)b * RWS + rq * 4 + lane) * 80 + e] = v;
        }
    }
}

// ---------------- fused dt_proj + softplus + selective scan ----------------
__global__ void __launch_bounds__(128) scan_k(const float* __restrict__ dtw_f,
                                              const float* __restrict__ dtw_b,
                                              const float* __restrict__ dtb_f,
                                              const float* __restrict__ dtb_b,
                                              const float* __restrict__ Alog_f,
                                              const float* __restrict__ Alog_b)
{
    __shared__ float xd[RWS * 80];
    __shared__ float dtws[128][49];

    const int dir = blockIdx.z;
    const int b = blockIdx.y;
    const int d0 = blockIdx.x * 128;
    const int tid = threadIdx.x;
    const int d = d0 + tid;

    const float* xdbl = g_xdbl[dir] + (size_t)b * RWS * 80;
    for (int i = tid; i < RWS * 80; i += 128) xd[i] = xdbl[i];

    const float* dtw = dir ? dtw_b : dtw_f;
    for (int idx = tid; idx < 128 * DTR; idx += 128) {
        const int row = idx / DTR, col = idx % DTR;
        dtws[row][col] = dtw[(size_t)d0 * DTR + idx];
    }
    __syncthreads();

    const float* Alog = (dir ? Alog_b : Alog_f) + (size_t)d * NS;
    const float bias = dir ? dtb_b[d] : dtb_f[d];

    float A[NS];
#pragma unroll
    for (int n = 0; n < NS; n++) A[n] = -expf(Alog[n]);

    const float A0 = A[0];
    bool chain = true;
#pragma unroll
    for (int n = 1; n < NS; n++)
        chain = chain && (fabsf(A[n] - (float)(n + 1) * A0) <= 1e-4f * fabsf(A[n]));

    float u[RWS];
    const float* up = g_xcomp[dir] + (size_t)b * RWS * DI + d;
#pragma unroll
    for (int r = 0; r < RWS; r++) u[r] = up[(size_t)r * DI];

    float h[NS];
#pragma unroll
    for (int n = 0; n < NS; n++) h[n] = 0.f;

    float* yp = g_y[dir] + (size_t)b * RWS * DI + d;
#pragma unroll 1
    for (int r = 0; r < RWS; r++) {
        float dt = bias;
#pragma unroll
        for (int rr = 0; rr < DTR; rr++) dt += xd[r * 80 + rr] * dtws[tid][rr];
        const float delta = fmaxf(dt, 0.f) + log1pf(__expf(-fabsf(dt)));
        const float du = delta * u[r];
        const float qch = __expf(delta * A0);
        float p = 1.f;
        float acc = 0.f;
#pragma unroll
        for (int n = 0; n < NS; n++) {
            float dA;
            if (chain) { p *= qch; dA = p; }
            else       { dA = __expf(delta * A[n]); }
            h[n] = dA * h[n] + du * xd[r * 80 + 48 + n];
            acc += h[n] * xd[r * 80 + 64 + n];
        }
        yp[(size_t)r * DI] = acc;
    }
}

// ---------------- combine + LayerNorm + SiLU(z) gate ----------------
__global__ void __launch_bounds__(256) ln_gate_k(const float* __restrict__ Dp,
                                                 const float* __restrict__ Dpb,
                                                 const float* __restrict__ gamma,
                                                 const float* __restrict__ beta)
{
    const int bl = blockIdx.x;
    const int b = bl >> 8;
    const int l = bl & 255;
    const int lb = 255 - l;
    const int rf = l >> 4, rb = lb >> 4;
    const int tid = threadIdx.x;

    const __half* xcf = g_xch[0] + ((size_t)b * LSEQ + l) * DI;
    const __half* xcb = g_xch[1] + ((size_t)b * LSEQ + lb) * DI;
    const float* yf = g_y[0] + ((size_t)b * RWS + rf) * DI;
    const float* yb = g_y[1] + ((size_t)b * RWS + rb) * DI;

    float v[6];
    float s = 0.f, s2 = 0.f;
#pragma unroll
    for (int i = 0; i < 6; i++) {
        const int d = tid + i * 256;
        const float cf = yf[d] + Dp[d] * __half2float(xcf[d]);
        const float cbv = yb[d] + Dpb[d] * __half2float(xcb[d]);
        const float val = 0.5f * (cf + cbv);
        v[i] = val;
        s += val;
        s2 += val * val;
    }

    __shared__ float red[16];
#pragma unroll
    for (int off = 16; off >= 1; off >>= 1) {
        s += __shfl_xor_sync(0xffffffffu, s, off);
        s2 += __shfl_xor_sync(0xffffffffu, s2, off);
    }
    const int warp = tid >> 5, lane = tid & 31;
    if (lane == 0) { red[warp] = s; red[warp + 8] = s2; }
    __syncthreads();
    if (warp == 0) {
        float a = (lane < 8) ? red[lane] : 0.f;
        float c = (lane < 8) ? red[lane + 8] : 0.f;
#pragma unroll
        for (int off = 4; off >= 1; off >>= 1) {
            a += __shfl_xor_sync(0xffffffffu, a, off);
            c += __shfl_xor_sync(0xffffffffu, c, off);
        }
        if (lane == 0) { red[0] = a; red[1] = c; }
    }
    __syncthreads();

    const float mean = red[0] * (1.f / DI);
    const float var = red[1] * (1.f / DI) - mean * mean;
    const float rstd = rsqrtf(var + 1e-5f);

#pragma unroll
    for (int i = 0; i < 6; i++) {
        const int d = tid + i * 256;
        const float g = (v[i] - mean) * rstd * gamma[d] + beta[d];
        const float zv = __half2float(g_zh[(size_t)bl * DI + d]);
        const float sz = __fdividef(zv, 1.f + __expf(-zv));
        g_gated[(size_t)bl * DI + d] = __float2half_rn(g * sz);
    }
}

// ---------------- launch ----------------
extern "C" void kernel_launch(void* const* d_in, const int* in_sizes, int n_in,
                              void* d_out, int out_size)
{
    const float* hs    = (const float*)d_in[0];
    const float* inw   = (const float*)d_in[1];
    const float* cw    = (const float*)d_in[2];
    const float* cb    = (const float*)d_in[3];
    const float* cwb   = (const float*)d_in[4];
    const float* cbb   = (const float*)d_in[5];
    const float* xpw   = (const float*)d_in[6];
    const float* xpwb  = (const float*)d_in[7];
    const float* dtw   = (const float*)d_in[8];
    const float* dtwb  = (const float*)d_in[9];
    const float* dtb   = (const float*)d_in[10];
    const float* dtbb  = (const float*)d_in[11];
    const float* Alog  = (const float*)d_in[12];
    const float* Alogb = (const float*)d_in[13];
    const float* Dp    = (const float*)d_in[14];
    const float* Dpb   = (const float*)d_in[15];
    const float* gam   = (const float*)d_in[16];
    const float* bet   = (const float*)d_in[17];
    const float* opw   = (const float*)d_in[18];
    float* out = (float*)d_out;

    __half *d_hsh, *d_wih, *d_woh;
    cudaGetSymbolAddress((void**)&d_hsh, g_hsh);
    cudaGetSymbolAddress((void**)&d_wih, g_wih);
    cudaGetSymbolAddress((void**)&d_woh, g_woh);

    cudaFuncSetAttribute(hgemm<1>, cudaFuncAttributeMaxDynamicSharedMemorySize, HG_SMEM_BYTES);
    cudaFuncSetAttribute(hgemm<2>, cudaFuncAttributeMaxDynamicSharedMemorySize, HG_SMEM_BYTES);

    // 0) convert fp32 inputs to half
    {
        const int n1 = B_SZ * LSEQ * DM / 4;      // hs
        const int n2 = 2 * DI * DM / 4;           // in_proj_w
        const int n3 = DM * DI / 4;               // out_proj_w
        f2h_k<<<(n1 + 255) / 256, 256>>>(hs, d_hsh, n1);
        f2h_k<<<(n2 + 255) / 256, 256>>>(inw, d_wih, n2);
        f2h_k<<<(n3 + 255) / 256, 256>>>(opw, d_woh, n3);
    }
    // 1) in_proj: (16384 x 768) x (3072 x 768)^T -> g_x | g_zh
    hgemm<1><<<dim3(3072 / 128, 16384 / 128), 256, HG_SMEM_BYTES>>>(nullptr, DM);
    // 2) depthwise conv + SiLU + block means
    conv_silu_k<<<dim3(DI / 16, B_SZ), 256>>>(cw, cb, cwb, cbb);
    // 3) x_proj
    xdbl_k<<<dim3(B_SZ * 4, 2), 256>>>(xpw, xpwb);
    // 4) dt_proj + selective scan
    scan_k<<<dim3(DI / 128, B_SZ, 2), 128>>>(dtw, dtwb, dtb, dtbb, Alog, Alogb);
    // 5) combine + LN + gate
    ln_gate_k<<<B_SZ * LSEQ, 256>>>(Dp, Dpb, gam, bet);
    // 6) out_proj: (16384 x 1536) x (768 x 1536)^T -> d_out
    hgemm<2><<<dim3(768 / 128, 16384 / 128), 256, HG_SMEM_BYTES>>>(out, DI);
}

// round 15
// speedup vs baseline: 7.6472x; 1.0334x over previous
#include <cuda_runtime.h>
#include <cuda_fp16.h>
#include <math.h>
#include <stdint.h>

#define B_SZ  64
#define DM    768
#define DI    1536
#define NS    16
#define LSEQ  256
#define RWS   16
#define DTR   48

// ---------------- scratch (static device arrays; no allocation) ----------------
__device__ float  g_x[B_SZ * LSEQ * DI];          // (b, l, d)
__device__ __half g_zh[B_SZ * LSEQ * DI];         // (b, l, d) half
__device__ __half g_xch[2][B_SZ * LSEQ * DI];     // conv+silu, half
__device__ float  g_xcomp[2][B_SZ * RWS * DI];    // (b, r, d)
__device__ float  g_xdbl[2][B_SZ * RWS * 80];     // (b, r, e)
__device__ float  g_y[2][B_SZ * RWS * DI];        // (b, r, d)
__device__ __half g_gated[B_SZ * LSEQ * DI];      // (b*l, d) half
__device__ __half g_hsh[B_SZ * LSEQ * DM];        // hidden_states half
__device__ __half g_wih[2 * DI * DM];             // in_proj_w half
__device__ __half g_woh[DM * DI];                 // out_proj_w half

// ---------------- helpers ----------------
__device__ __forceinline__ void mma_f16(float* c, const unsigned* a, const unsigned* b) {
    asm volatile(
        "mma.sync.aligned.m16n8k16.row.col.f32.f16.f16.f32 "
        "{%0,%1,%2,%3}, {%4,%5,%6,%7}, {%8,%9}, {%0,%1,%2,%3};"
        : "+f"(c[0]), "+f"(c[1]), "+f"(c[2]), "+f"(c[3])
        : "r"(a[0]), "r"(a[1]), "r"(a[2]), "r"(a[3]), "r"(b[0]), "r"(b[1]));
}
__device__ __forceinline__ void ldsm_x4(unsigned& r0, unsigned& r1, unsigned& r2, unsigned& r3,
                                        uint32_t addr) {
    asm volatile("ldmatrix.sync.aligned.m8n8.x4.shared.b16 {%0,%1,%2,%3}, [%4];"
                 : "=r"(r0), "=r"(r1), "=r"(r2), "=r"(r3) : "r"(addr));
}
__device__ __forceinline__ unsigned pack_half2(float x, float y) {
    __half2 h = __floats2half2_rn(x, y);
    return *(unsigned*)&h;
}
__device__ __forceinline__ void cp16(uint32_t dst, const void* src) {
    asm volatile("cp.async.cg.shared.global [%0], [%1], 16;" :: "r"(dst), "l"(src));
}
#define CP_COMMIT() asm volatile("cp.async.commit_group;" ::: "memory")
#define CP_WAIT1()  asm volatile("cp.async.wait_group 1;" ::: "memory")
#define CP_WAIT0()  asm volatile("cp.async.wait_group 0;" ::: "memory")

// ---------------- fp32 -> fp16 convert (vectorized) ----------------
__global__ void __launch_bounds__(256) f2h_k(const float* __restrict__ src,
                                             __half* __restrict__ dst, int n4)
{
    const int i = blockIdx.x * 256 + threadIdx.x;
    if (i < n4) {
        float4 v = ((const float4*)src)[i];
        uint2 o;
        o.x = pack_half2(v.x, v.y);
        o.y = pack_half2(v.z, v.w);
        ((uint2*)dst)[i] = o;
    }
}

// ---------------- fp16 GEMM (3-stage cp.async + ldmatrix) ----------------
// Block 128x128, BK=32, 256 threads = 8 warps (2m x 4n), warp tile 64x32. 3 smem stages.
// MODE 1: A=g_hsh, W=g_wih; split epilogue -> g_x (f32) / g_zh (half)  (K=768,  N=3072)
// MODE 2: A=g_gated, W=g_woh; C=out f32                                 (K=1536, N=768)
#define HG_STAGES 3
#define HG_STAGE_HALVES (128 * 40)
#define HG_STAGE_BYTES (HG_STAGE_HALVES * 2)
#define HG_SMEM_BYTES (HG_STAGES * 2 * HG_STAGE_BYTES)

template<int MODE>
__global__ void __launch_bounds__(256, 2) hgemm(float* __restrict__ C, int K)
{
    extern __shared__ __half sm[];
    __half* Asm = sm;                                  // A stages [0..2]
    __half* Bsm = sm + HG_STAGES * HG_STAGE_HALVES;    // B stages [0..2]

    const __half* Ah = (MODE == 1) ? (const __half*)g_hsh : (const __half*)g_gated;
    const __half* Wh = (MODE == 1) ? (const __half*)g_wih : (const __half*)g_woh;

    const int tid = threadIdx.x;
    const int warp = tid >> 5, lane = tid & 31;
    const int m0 = blockIdx.y * 128, n0 = blockIdx.x * 128;
    const int wm = (warp >> 2) * 64;       // 0 or 64
    const int wn = (warp & 3) * 32;        // 0..96
    const int grp = lane >> 2, tig = lane & 3;

    // ---- cp.async load mapping: 4 x 16B per thread per stage ----
    const int lchunk = tid & 3;            // 16B chunk (8 halves) within 64-half row
    const int lrow = tid >> 2;             // 0..63

    const __half* Abase = Ah + (size_t)(m0 + lrow) * K + lchunk * 8;
    const __half* Bbase = Wh + (size_t)(n0 + lrow) * K + lchunk * 8;
    const size_t row64 = (size_t)64 * K;

    uint32_t asd[HG_STAGES][2], bsd[HG_STAGES][2];
#pragma unroll
    for (int s = 0; s < HG_STAGES; s++) {
        asd[s][0] = (uint32_t)__cvta_generic_to_shared(Asm + s * HG_STAGE_HALVES + lrow * 40 + lchunk * 8);
        asd[s][1] = (uint32_t)__cvta_generic_to_shared(Asm + s * HG_STAGE_HALVES + (lrow + 64) * 40 + lchunk * 8);
        bsd[s][0] = (uint32_t)__cvta_generic_to_shared(Bsm + s * HG_STAGE_HALVES + lrow * 40 + lchunk * 8);
        bsd[s][1] = (uint32_t)__cvta_generic_to_shared(Bsm + s * HG_STAGE_HALVES + (lrow + 64) * 40 + lchunk * 8);
    }

    // ---- ldmatrix per-thread addresses (stage 0, kc 0; offsets added in-loop) ----
    // A x4: matrices [rows0-7,k0-7][rows8-15,k0-7][rows0-7,k8-15][rows8-15,k8-15]
    //   lanes 0-15 -> rows (lane&15), k+0 ; lanes 16-31 -> rows (lane&15), k+8
    const uint32_t a_lds0 = (uint32_t)__cvta_generic_to_shared(
        Asm + ((wm + (lane & 15)) * 40 + 8 * (lane >> 4)));
    // B x4 (covers nt pair): [n0-7,k0-7][n0-7,k8-15][n8-15,k0-7][n8-15,k8-15]
    //   row = wn + p*16 + 8*(lane>=16) + (lane&7); khalf = (lane>>3)&1
    const uint32_t b_lds0 = (uint32_t)__cvta_generic_to_shared(
        Bsm + ((wn + ((lane >> 4) << 3) + (lane & 7)) * 40 + 8 * ((lane >> 3) & 1)));

    float acc[4][4][4];
#pragma unroll
    for (int i = 0; i < 4; i++)
#pragma unroll
        for (int j = 0; j < 4; j++)
#pragma unroll
            for (int r = 0; r < 4; r++) acc[i][j][r] = 0.f;

    const int NIT = K / 32;

    // prologue: stages 0 and 1
#pragma unroll
    for (int s = 0; s < 2; s++) {
        const int k0 = s * 32;
        cp16(asd[s][0], Abase + k0);
        cp16(asd[s][1], Abase + row64 + k0);
        cp16(bsd[s][0], Bbase + k0);
        cp16(bsd[s][1], Bbase + row64 + k0);
        CP_COMMIT();
    }

    int st = 0;
    for (int it = 0; it < NIT; ++it) {
        if (it + 2 < NIT) CP_WAIT1();
        else              CP_WAIT0();
        __syncthreads();

        // issue stage it+2 (buffer consumed in iteration it-1; barrier orders it)
        if (it + 2 < NIT) {
            const int ns = (st + 2 >= HG_STAGES) ? st + 2 - HG_STAGES : st + 2;
            const int k0 = (it + 2) * 32;
            cp16(asd[ns][0], Abase + k0);
            cp16(asd[ns][1], Abase + row64 + k0);
            cp16(bsd[ns][0], Bbase + k0);
            cp16(bsd[ns][1], Bbase + row64 + k0);
            CP_COMMIT();
        }

        const uint32_t stoff = st * HG_STAGE_BYTES;
        const uint32_t a_st = a_lds0 + stoff;
        const uint32_t b_st = b_lds0 + stoff;
#pragma unroll
        for (int ks = 0; ks < 2; ks++) {
            const uint32_t kb = ks * 32;     // 16 halves = 32 bytes
            unsigned afr[4][4], bfr[4][2];
#pragma unroll
            for (int mt = 0; mt < 4; mt++)
                ldsm_x4(afr[mt][0], afr[mt][1], afr[mt][2], afr[mt][3],
                        a_st + mt * 1280 + kb);
#pragma unroll
            for (int p = 0; p < 2; p++)
                ldsm_x4(bfr[2 * p][0], bfr[2 * p][1], bfr[2 * p + 1][0], bfr[2 * p + 1][1],
                        b_st + p * 1280 + kb);
#pragma unroll
            for (int mt = 0; mt < 4; mt++)
#pragma unroll
                for (int nt = 0; nt < 4; nt++)
                    mma_f16(acc[mt][nt], afr[mt], bfr[nt]);
        }
        st = (st + 1 >= HG_STAGES) ? 0 : st + 1;
    }

    // epilogue
#pragma unroll
    for (int mt = 0; mt < 4; mt++) {
#pragma unroll
        for (int nt = 0; nt < 4; nt++) {
            const int m = m0 + wm + mt * 16 + grp;
            const int n = n0 + wn + nt * 8 + 2 * tig;
            if (MODE == 1) {
                if (n0 < DI) {
                    *(float2*)&g_x[(size_t)m * DI + n] = make_float2(acc[mt][nt][0], acc[mt][nt][1]);
                    *(float2*)&g_x[(size_t)(m + 8) * DI + n] = make_float2(acc[mt][nt][2], acc[mt][nt][3]);
                } else {
                    const int nn = n - DI;
                    *(unsigned*)&g_zh[(size_t)m * DI + nn] = pack_half2(acc[mt][nt][0], acc[mt][nt][1]);
                    *(unsigned*)&g_zh[(size_t)(m + 8) * DI + nn] = pack_half2(acc[mt][nt][2], acc[mt][nt][3]);
                }
            } else {
                *(float2*)&C[(size_t)m * 768 + n] = make_float2(acc[mt][nt][0], acc[mt][nt][1]);
                *(float2*)&C[(size_t)(m + 8) * 768 + n] = make_float2(acc[mt][nt][2], acc[mt][nt][3]);
            }
        }
    }
}

// ---------------- conv + SiLU + 16-block mean (both directions, tiled) ----------------
__global__ void __launch_bounds__(256) conv_silu_k(const float* __restrict__ cw,
                                                   const float* __restrict__ cb,
                                                   const float* __restrict__ cwb,
                                                   const float* __restrict__ cbb)
{
    __shared__ float X[256][17];
    __shared__ float F[256][17];

    const int d0 = blockIdx.x * 16;
    const int b = blockIdx.y;
    const int tid = threadIdx.x;

#pragma unroll
    for (int i = 0; i < 4; i++) {
        const int idx = tid + 256 * i;
        const int l = idx >> 2, q = idx & 3;
        float4 v = *(const float4*)&g_x[((size_t)b * LSEQ + l) * DI + d0 + 4 * q];
        X[l][4 * q + 0] = v.x; X[l][4 * q + 1] = v.y;
        X[l][4 * q + 2] = v.z; X[l][4 * q + 3] = v.w;
    }
    __syncthreads();

    const int sub = tid >> 4;
    const int d = tid & 15;
    const int dg = d0 + d;

    {
        float w[4];
#pragma unroll
        for (int k = 0; k < 4; k++) w[k] = cw[dg * 4 + k];
        const float bias = cb[dg];
#pragma unroll
        for (int i = 0; i < 16; i++) {
            const int l = i * 16 + sub;
            float a = bias;
#pragma unroll
            for (int k = 0; k < 4; k++) {
                const int idx = l - 3 + k;
                if (idx >= 0) a += w[k] * X[idx][d];
            }
            const float s = __fdividef(a, 1.f + __expf(-a));
            F[l][d] = s;
            g_xch[0][((size_t)b * LSEQ + l) * DI + dg] = __float2half_rn(s);
        }
    }
    __syncthreads();
    {
        const int r = tid >> 4;
        float s = 0.f;
#pragma unroll
        for (int j = 0; j < 16; j++) s += F[16 * r + j][d];
        g_xcomp[0][((size_t)b * RWS + r) * DI + dg] = s * (1.f / 16.f);
    }
    __syncthreads();

    {
        float w[4];
#pragma unroll
        for (int k = 0; k < 4; k++) w[k] = cwb[dg * 4 + k];
        const float bias = cbb[dg];
#pragma unroll
        for (int i = 0; i < 16; i++) {
            const int l = i * 16 + sub;
            float a = bias;
#pragma unroll
            for (int k = 0; k < 4; k++) {
                const int idx = l - 3 + k;
                if (idx >= 0) a += w[k] * X[255 - idx][d];
            }
            const float s = __fdividef(a, 1.f + __expf(-a));
            F[l][d] = s;
            g_xch[1][((size_t)b * LSEQ + l) * DI + dg] = __float2half_rn(s);
        }
    }
    __syncthreads();
    {
        const int r = tid >> 4;
        float s = 0.f;
#pragma unroll
        for (int j = 0; j < 16; j++) s += F[16 * r + j][d];
        g_xcomp[1][((size_t)b * RWS + r) * DI + dg] = s * (1.f / 16.f);
    }
}

// ---------------- x_proj: 4 r per block ----------------
__global__ void __launch_bounds__(256) xdbl_k(const float* __restrict__ xpw_f,
                                              const float* __restrict__ xpw_b)
{
    __shared__ float xs[4 * DI];
    const int dir = blockIdx.y;
    const int b = blockIdx.x >> 2;
    const int rq = blockIdx.x & 3;

    const float* src = g_xcomp[dir] + ((size_t)b * RWS + rq * 4) * DI;
    for (int i = threadIdx.x; i < 4 * DI; i += 256) xs[i] = src[i];
    __syncthreads();

    const float* xpw = dir ? xpw_b : xpw_f;
    const int warp = threadIdx.x >> 5, lane = threadIdx.x & 31;
    for (int e = warp; e < 80; e += 8) {
        const float* wrow = xpw + (size_t)e * DI;
        float s0 = 0.f, s1 = 0.f, s2 = 0.f, s3 = 0.f;
        for (int k = lane; k < DI; k += 32) {
            const float w = wrow[k];
            s0 += w * xs[k];
            s1 += w * xs[DI + k];
            s2 += w * xs[2 * DI + k];
            s3 += w * xs[3 * DI + k];
        }
#pragma unroll
        for (int off = 16; off >= 1; off >>= 1) {
            s0 += __shfl_xor_sync(0xffffffffu, s0, off);
            s1 += __shfl_xor_sync(0xffffffffu, s1, off);
            s2 += __shfl_xor_sync(0xffffffffu, s2, off);
            s3 += __shfl_xor_sync(0xffffffffu, s3, off);
        }
        if (lane < 4) {
            const float v = (lane == 0) ? s0 : (lane == 1) ? s1 : (lane == 2) ? s2 : s3;
            g_xdbl[dir][((size_t)b * RWS + rq * 4 + lane) * 80 + e] = v;
        }
    }
}

// ---------------- fused dt_proj + softplus + selective scan ----------------
__global__ void __launch_bounds__(128) scan_k(const float* __restrict__ dtw_f,
                                              const float* __restrict__ dtw_b,
                                              const float* __restrict__ dtb_f,
                                              const float* __restrict__ dtb_b,
                                              const float* __restrict__ Alog_f,
                                              const float* __restrict__ Alog_b)
{
    __shared__ float xd[RWS * 80];
    __shared__ float dtws[128][49];

    const int dir = blockIdx.z;
    const int b = blockIdx.y;
    const int d0 = blockIdx.x * 128;
    const int tid = threadIdx.x;
    const int d = d0 + tid;

    const float* xdbl = g_xdbl[dir] + (size_t)b * RWS * 80;
    for (int i = tid; i < RWS * 80; i += 128) xd[i] = xdbl[i];

    const float* dtw = dir ? dtw_b : dtw_f;
    for (int idx = tid; idx < 128 * DTR; idx += 128) {
        const int row = idx / DTR, col = idx % DTR;
        dtws[row][col] = dtw[(size_t)d0 * DTR + idx];
    }
    __syncthreads();

    const float* Alog = (dir ? Alog_b : Alog_f) + (size_t)d * NS;
    const float bias = dir ? dtb_b[d] : dtb_f[d];

    float A[NS];
#pragma unroll
    for (int n = 0; n < NS; n++) A[n] = -expf(Alog[n]);

    const float A0 = A[0];
    bool chain = true;
#pragma unroll
    for (int n = 1; n < NS; n++)
        chain = chain && (fabsf(A[n] - (float)(n + 1) * A0) <= 1e-4f * fabsf(A[n]));

    float u[RWS];
    const float* up = g_xcomp[dir] + (size_t)b * RWS * DI + d;
#pragma unroll
    for (int r = 0; r < RWS; r++) u[r] = up[(size_t)r * DI];

    float h[NS];
#pragma unroll
    for (int n = 0; n < NS; n++) h[n] = 0.f;

    float* yp = g_y[dir] + (size_t)b * RWS * DI + d;
#pragma unroll 1
    for (int r = 0; r < RWS; r++) {
        float dt = bias;
#pragma unroll
        for (int rr = 0; rr < DTR; rr++) dt += xd[r * 80 + rr] * dtws[tid][rr];
        const float delta = fmaxf(dt, 0.f) + log1pf(__expf(-fabsf(dt)));
        const float du = delta * u[r];
        const float qch = __expf(delta * A0);
        float p = 1.f;
        float acc = 0.f;
#pragma unroll
        for (int n = 0; n < NS; n++) {
            float dA;
            if (chain) { p *= qch; dA = p; }
            else       { dA = __expf(delta * A[n]); }
            h[n] = dA * h[n] + du * xd[r * 80 + 48 + n];
            acc += h[n] * xd[r * 80 + 64 + n];
        }
        yp[(size_t)r * DI] = acc;
    }
}

// ---------------- combine + LayerNorm + SiLU(z) gate ----------------
__global__ void __launch_bounds__(256) ln_gate_k(const float* __restrict__ Dp,
                                                 const float* __restrict__ Dpb,
                                                 const float* __restrict__ gamma,
                                                 const float* __restrict__ beta)
{
    const int bl = blockIdx.x;
    const int b = bl >> 8;
    const int l = bl & 255;
    const int lb = 255 - l;
    const int rf = l >> 4, rb = lb >> 4;
    const int tid = threadIdx.x;

    const __half* xcf = g_xch[0] + ((size_t)b * LSEQ + l) * DI;
    const __half* xcb = g_xch[1] + ((size_t)b * LSEQ + lb) * DI;
    const float* yf = g_y[0] + ((size_t)b * RWS + rf) * DI;
    const float* yb = g_y[1] + ((size_t)b * RWS + rb) * DI;

    float v[6];
    float s = 0.f, s2 = 0.f;
#pragma unroll
    for (int i = 0; i < 6; i++) {
        const int d = tid + i * 256;
        const float cf = yf[d] + Dp[d] * __half2float(xcf[d]);
        const float cbv = yb[d] + Dpb[d] * __half2float(xcb[d]);
        const float val = 0.5f * (cf + cbv);
        v[i] = val;
        s += val;
        s2 += val * val;
    }

    __shared__ float red[16];
#pragma unroll
    for (int off = 16; off >= 1; off >>= 1) {
        s += __shfl_xor_sync(0xffffffffu, s, off);
        s2 += __shfl_xor_sync(0xffffffffu, s2, off);
    }
    const int warp = tid >> 5, lane = tid & 31;
    if (lane == 0) { red[warp] = s; red[warp + 8] = s2; }
    __syncthreads();
    if (warp == 0) {
        float a = (lane < 8) ? red[lane] : 0.f;
        float c = (lane < 8) ? red[lane + 8] : 0.f;
#pragma unroll
        for (int off = 4; off >= 1; off >>= 1) {
            a += __shfl_xor_sync(0xffffffffu, a, off);
            c += __shfl_xor_sync(0xffffffffu, c, off);
        }
        if (lane == 0) { red[0] = a; red[1] = c; }
    }
    __syncthreads();

    const float mean = red[0] * (1.f / DI);
    const float var = red[1] * (1.f / DI) - mean * mean;
    const float rstd = rsqrtf(var + 1e-5f);

#pragma unroll
    for (int i = 0; i < 6; i++) {
        const int d = tid + i * 256;
        const float g = (v[i] - mean) * rstd * gamma[d] + beta[d];
        const float zv = __half2float(g_zh[(size_t)bl * DI + d]);
        const float sz = __fdividef(zv, 1.f + __expf(-zv));
        g_gated[(size_t)bl * DI + d] = __float2half_rn(g * sz);
    }
}

// ---------------- launch ----------------
extern "C" void kernel_launch(void* const* d_in, const int* in_sizes, int n_in,
                              void* d_out, int out_size)
{
    const float* hs    = (const float*)d_in[0];
    const float* inw   = (const float*)d_in[1];
    const float* cw    = (const float*)d_in[2];
    const float* cb    = (const float*)d_in[3];
    const float* cwb   = (const float*)d_in[4];
    const float* cbb   = (const float*)d_in[5];
    const float* xpw   = (const float*)d_in[6];
    const float* xpwb  = (const float*)d_in[7];
    const float* dtw   = (const float*)d_in[8];
    const float* dtwb  = (const float*)d_in[9];
    const float* dtb   = (const float*)d_in[10];
    const float* dtbb  = (const float*)d_in[11];
    const float* Alog  = (const float*)d_in[12];
    const float* Alogb = (const float*)d_in[13];
    const float* Dp    = (const float*)d_in[14];
    const float* Dpb   = (const float*)d_in[15];
    const float* gam   = (const float*)d_in[16];
    const float* bet   = (const float*)d_in[17];
    const float* opw   = (const float*)d_in[18];
    float* out = (float*)d_out;

    __half *d_hsh, *d_wih, *d_woh;
    cudaGetSymbolAddress((void**)&d_hsh, g_hsh);
    cudaGetSymbolAddress((void**)&d_wih, g_wih);
    cudaGetSymbolAddress((void**)&d_woh, g_woh);

    cudaFuncSetAttribute(hgemm<1>, cudaFuncAttributeMaxDynamicSharedMemorySize, HG_SMEM_BYTES);
    cudaFuncSetAttribute(hgemm<2>, cudaFuncAttributeMaxDynamicSharedMemorySize, HG_SMEM_BYTES);

    // 0) convert fp32 inputs to half
    {
        const int n1 = B_SZ * LSEQ * DM / 4;      // hs
        const int n2 = 2 * DI * DM / 4;           // in_proj_w
        const int n3 = DM * DI / 4;               // out_proj_w
        f2h_k<<<(n1 + 255) / 256, 256>>>(hs, d_hsh, n1);
        f2h_k<<<(n2 + 255) / 256, 256>>>(inw, d_wih, n2);
        f2h_k<<<(n3 + 255) / 256, 256>>>(opw, d_woh, n3);
    }
    // 1) in_proj: (16384 x 768) x (3072 x 768)^T -> g_x | g_zh
    hgemm<1><<<dim3(3072 / 128, 16384 / 128), 256, HG_SMEM_BYTES>>>(nullptr, DM);
    // 2) depthwise conv + SiLU + block means
    conv_silu_k<<<dim3(DI / 16, B_SZ), 256>>>(cw, cb, cwb, cbb);
    // 3) x_proj
    xdbl_k<<<dim3(B_SZ * 4, 2), 256>>>(xpw, xpwb);
    // 4) dt_proj + selective scan
    scan_k<<<dim3(DI / 128, B_SZ, 2), 128>>>(dtw, dtwb, dtb, dtbb, Alog, Alogb);
    // 5) combine + LN + gate
    ln_gate_k<<<B_SZ * LSEQ, 256>>>(Dp, Dpb, gam, bet);
    // 6) out_proj: (16384 x 1536) x (768 x 1536)^T -> d_out
    hgemm<2><<<dim3(768 / 128, 16384 / 128), 256, HG_SMEM_BYTES>>>(out, DI);
}

// round 16
// speedup vs baseline: 8.6147x; 1.1265x over previous
#include <cuda_runtime.h>
#include <cuda_fp16.h>
#include <math.h>
#include <stdint.h>

#define B_SZ  64
#define DM    768
#define DI    1536
#define NS    16
#define LSEQ  256
#define RWS   16
#define DTR   48

// ---------------- scratch (static device arrays; no allocation) ----------------
__device__ float  g_x[B_SZ * LSEQ * DI];          // (b, l, d)
__device__ __half g_zh[B_SZ * LSEQ * DI];         // (b, l, d) half
__device__ __half g_xch[2][B_SZ * LSEQ * DI];     // conv+silu, half
__device__ float  g_xcomp[2][B_SZ * RWS * DI];    // (b, r, d)
__device__ float  g_xdbl[2][B_SZ * RWS * 80];     // (b, r, e)
__device__ float  g_y[2][B_SZ * RWS * DI];        // (b, r, d)
__device__ __half g_gated[B_SZ * LSEQ * DI];      // (b*l, d) half
__device__ __half g_hsh[B_SZ * LSEQ * DM];        // hidden_states half
__device__ __half g_wih[2 * DI * DM];             // in_proj_w half
__device__ __half g_woh[DM * DI];                 // out_proj_w half

// ---------------- helpers ----------------
__device__ __forceinline__ void mma_f16(float* c, const unsigned* a, const unsigned* b) {
    asm volatile(
        "mma.sync.aligned.m16n8k16.row.col.f32.f16.f16.f32 "
        "{%0,%1,%2,%3}, {%4,%5,%6,%7}, {%8,%9}, {%0,%1,%2,%3};"
        : "+f"(c[0]), "+f"(c[1]), "+f"(c[2]), "+f"(c[3])
        : "r"(a[0]), "r"(a[1]), "r"(a[2]), "r"(a[3]), "r"(b[0]), "r"(b[1]));
}
__device__ __forceinline__ void ldsm_x4(unsigned& r0, unsigned& r1, unsigned& r2, unsigned& r3,
                                        uint32_t addr) {
    asm volatile("ldmatrix.sync.aligned.m8n8.x4.shared.b16 {%0,%1,%2,%3}, [%4];"
                 : "=r"(r0), "=r"(r1), "=r"(r2), "=r"(r3) : "r"(addr));
}
__device__ __forceinline__ unsigned pack_half2(float x, float y) {
    __half2 h = __floats2half2_rn(x, y);
    return *(unsigned*)&h;
}
__device__ __forceinline__ void cp16(uint32_t dst, const void* src) {
    asm volatile("cp.async.cg.shared.global [%0], [%1], 16;" :: "r"(dst), "l"(src));
}
#define CP_COMMIT() asm volatile("cp.async.commit_group;" ::: "memory")
#define CP_WAIT0()  asm volatile("cp.async.wait_group 0;" ::: "memory")

// ---------------- fp32 -> fp16 convert (vectorized) ----------------
__global__ void __launch_bounds__(256) f2h_k(const float* __restrict__ src,
                                             __half* __restrict__ dst, int n4)
{
    const int i = blockIdx.x * 256 + threadIdx.x;
    if (i < n4) {
        float4 v = ((const float4*)src)[i];
        uint2 o;
        o.x = pack_half2(v.x, v.y);
        o.y = pack_half2(v.z, v.w);
        ((uint2*)dst)[i] = o;
    }
}

// ---------------- fp16 GEMM (BK=64, 2-stage cp.async + ldmatrix) ----------------
// Block 128x128, BK=64, 256 threads = 8 warps (2m x 4n), warp tile 64x32.
// MODE 1: A=g_hsh, W=g_wih; split epilogue -> g_x (f32) / g_zh (half)  (K=768,  N=3072)
// MODE 2: A=g_gated, W=g_woh; C=out f32                                 (K=1536, N=768)
#define HG_BK 64
#define HG_RS 72                                   // row stride in halves (64 + 8 pad)
#define HG_STAGE_HALVES (128 * HG_RS)              // 9216 halves = 18 KB
#define HG_STAGE_BYTES (HG_STAGE_HALVES * 2)
#define HG_SMEM_BYTES (2 * 2 * HG_STAGE_BYTES)     // 2 stages x (A+B) = 73728 B

template<int MODE>
__global__ void __launch_bounds__(256, 2) hgemm(float* __restrict__ C, int K)
{
    extern __shared__ __half sm[];
    __half* Asm = sm;                               // A stages 0,1
    __half* Bsm = sm + 2 * HG_STAGE_HALVES;         // B stages 0,1

    const __half* Ah = (MODE == 1) ? (const __half*)g_hsh : (const __half*)g_gated;
    const __half* Wh = (MODE == 1) ? (const __half*)g_wih : (const __half*)g_woh;

    const int tid = threadIdx.x;
    const int warp = tid >> 5, lane = tid & 31;
    const int m0 = blockIdx.y * 128, n0 = blockIdx.x * 128;
    const int wm = (warp >> 2) * 64;       // 0 or 64
    const int wn = (warp & 3) * 32;        // 0..96
    const int grp = lane >> 2, tig = lane & 3;

    // ---- cp.async mapping: 128 rows x 128B per matrix per stage ----
    // thread -> (row = tid>>3 in 0..31, chunk = tid&7); 4 row-groups of 32.
    const int lchunk = tid & 7;            // 16B chunk within 128B row
    const int lrow = tid >> 3;             // 0..31

    const __half* Abase = Ah + (size_t)(m0 + lrow) * K + lchunk * 8;
    const __half* Bbase = Wh + (size_t)(n0 + lrow) * K + lchunk * 8;
    const size_t row32 = (size_t)32 * K;

    uint32_t a_cp[2], b_cp[2];
#pragma unroll
    for (int s = 0; s < 2; s++) {
        a_cp[s] = (uint32_t)__cvta_generic_to_shared(Asm + s * HG_STAGE_HALVES + lrow * HG_RS + lchunk * 8);
        b_cp[s] = (uint32_t)__cvta_generic_to_shared(Bsm + s * HG_STAGE_HALVES + lrow * HG_RS + lchunk * 8);
    }
    const uint32_t grp_stride = 32 * HG_RS * 2;    // bytes per 32-row group

    // ---- ldmatrix per-thread addresses (stage 0, ks 0) ----
    const uint32_t a_lds0 = (uint32_t)__cvta_generic_to_shared(
        Asm + ((wm + (lane & 15)) * HG_RS + 8 * (lane >> 4)));
    const uint32_t b_lds0 = (uint32_t)__cvta_generic_to_shared(
        Bsm + ((wn + ((lane >> 4) << 3) + (lane & 7)) * HG_RS + 8 * ((lane >> 3) & 1)));

    float acc[4][4][4];
#pragma unroll
    for (int i = 0; i < 4; i++)
#pragma unroll
        for (int j = 0; j < 4; j++)
#pragma unroll
            for (int r = 0; r < 4; r++) acc[i][j][r] = 0.f;

    const int NIT = K / HG_BK;

    // prologue: fill stage 0
#pragma unroll
    for (int g = 0; g < 4; g++) {
        cp16(a_cp[0] + g * grp_stride, Abase + (size_t)g * row32);
        cp16(b_cp[0] + g * grp_stride, Bbase + (size_t)g * row32);
    }
    CP_COMMIT();

    for (int it = 0; it < NIT; ++it) {
        CP_WAIT0();
        __syncthreads();

        // issue next stage into the other buffer (its data was consumed in it-1)
        if (it + 1 < NIT) {
            const int ns = (it + 1) & 1;
            const int k0 = (it + 1) * HG_BK;
#pragma unroll
            for (int g = 0; g < 4; g++) {
                cp16(a_cp[ns] + g * grp_stride, Abase + k0 + (size_t)g * row32);
                cp16(b_cp[ns] + g * grp_stride, Bbase + k0 + (size_t)g * row32);
            }
            CP_COMMIT();
        }

        const uint32_t stoff = (it & 1) * HG_STAGE_BYTES;
        const uint32_t a_st = a_lds0 + stoff;
        const uint32_t b_st = b_lds0 + stoff;
#pragma unroll
        for (int ks = 0; ks < 4; ks++) {
            const uint32_t kb = ks * 32;     // 16 halves = 32 bytes per ks step
            unsigned afr[4][4], bfr[4][2];
#pragma unroll
            for (int mt = 0; mt < 4; mt++)
                ldsm_x4(afr[mt][0], afr[mt][1], afr[mt][2], afr[mt][3],
                        a_st + mt * (16 * HG_RS * 2) + kb);
#pragma unroll
            for (int p = 0; p < 2; p++)
                ldsm_x4(bfr[2 * p][0], bfr[2 * p][1], bfr[2 * p + 1][0], bfr[2 * p + 1][1],
                        b_st + p * (16 * HG_RS * 2) + kb);
#pragma unroll
            for (int mt = 0; mt < 4; mt++)
#pragma unroll
                for (int nt = 0; nt < 4; nt++)
                    mma_f16(acc[mt][nt], afr[mt], bfr[nt]);
        }
    }

    // epilogue
#pragma unroll
    for (int mt = 0; mt < 4; mt++) {
#pragma unroll
        for (int nt = 0; nt < 4; nt++) {
            const int m = m0 + wm + mt * 16 + grp;
            const int n = n0 + wn + nt * 8 + 2 * tig;
            if (MODE == 1) {
                if (n0 < DI) {
                    *(float2*)&g_x[(size_t)m * DI + n] = make_float2(acc[mt][nt][0], acc[mt][nt][1]);
                    *(float2*)&g_x[(size_t)(m + 8) * DI + n] = make_float2(acc[mt][nt][2], acc[mt][nt][3]);
                } else {
                    const int nn = n - DI;
                    *(unsigned*)&g_zh[(size_t)m * DI + nn] = pack_half2(acc[mt][nt][0], acc[mt][nt][1]);
                    *(unsigned*)&g_zh[(size_t)(m + 8) * DI + nn] = pack_half2(acc[mt][nt][2], acc[mt][nt][3]);
                }
            } else {
                *(float2*)&C[(size_t)m * 768 + n] = make_float2(acc[mt][nt][0], acc[mt][nt][1]);
                *(float2*)&C[(size_t)(m + 8) * 768 + n] = make_float2(acc[mt][nt][2], acc[mt][nt][3]);
            }
        }
    }
}

// ---------------- conv + SiLU + 16-block mean (both directions, tiled) ----------------
__global__ void __launch_bounds__(256) conv_silu_k(const float* __restrict__ cw,
                                                   const float* __restrict__ cb,
                                                   const float* __restrict__ cwb,
                                                   const float* __restrict__ cbb)
{
    __shared__ float X[256][17];
    __shared__ float F[256][17];

    const int d0 = blockIdx.x * 16;
    const int b = blockIdx.y;
    const int tid = threadIdx.x;

#pragma unroll
    for (int i = 0; i < 4; i++) {
        const int idx = tid + 256 * i;
        const int l = idx >> 2, q = idx & 3;
        float4 v = *(const float4*)&g_x[((size_t)b * LSEQ + l) * DI + d0 + 4 * q];
        X[l][4 * q + 0] = v.x; X[l][4 * q + 1] = v.y;
        X[l][4 * q + 2] = v.z; X[l][4 * q + 3] = v.w;
    }
    __syncthreads();

    const int sub = tid >> 4;
    const int d = tid & 15;
    const int dg = d0 + d;

    {
        float w[4];
#pragma unroll
        for (int k = 0; k < 4; k++) w[k] = cw[dg * 4 + k];
        const float bias = cb[dg];
#pragma unroll
        for (int i = 0; i < 16; i++) {
            const int l = i * 16 + sub;
            float a = bias;
#pragma unroll
            for (int k = 0; k < 4; k++) {
                const int idx = l - 3 + k;
                if (idx >= 0) a += w[k] * X[idx][d];
            }
            const float s = __fdividef(a, 1.f + __expf(-a));
            F[l][d] = s;
            g_xch[0][((size_t)b * LSEQ + l) * DI + dg] = __float2half_rn(s);
        }
    }
    __syncthreads();
    {
        const int r = tid >> 4;
        float s = 0.f;
#pragma unroll
        for (int j = 0; j < 16; j++) s += F[16 * r + j][d];
        g_xcomp[0][((size_t)b * RWS + r) * DI + dg] = s * (1.f / 16.f);
    }
    __syncthreads();

    {
        float w[4];
#pragma unroll
        for (int k = 0; k < 4; k++) w[k] = cwb[dg * 4 + k];
        const float bias = cbb[dg];
#pragma unroll
        for (int i = 0; i < 16; i++) {
            const int l = i * 16 + sub;
            float a = bias;
#pragma unroll
            for (int k = 0; k < 4; k++) {
                const int idx = l - 3 + k;
                if (idx >= 0) a += w[k] * X[255 - idx][d];
            }
            const float s = __fdividef(a, 1.f + __expf(-a));
            F[l][d] = s;
            g_xch[1][((size_t)b * LSEQ + l) * DI + dg] = __float2half_rn(s);
        }
    }
    __syncthreads();
    {
        const int r = tid >> 4;
        float s = 0.f;
#pragma unroll
        for (int j = 0; j < 16; j++) s += F[16 * r + j][d];
        g_xcomp[1][((size_t)b * RWS + r) * DI + dg] = s * (1.f / 16.f);
    }
}

// ---------------- x_proj: 4 r per block ----------------
__global__ void __launch_bounds__(256) xdbl_k(const float* __restrict__ xpw_f,
                                              const float* __restrict__ xpw_b)
{
    __shared__ float xs[4 * DI];
    const int dir = blockIdx.y;
    const int b = blockIdx.x >> 2;
    const int rq = blockIdx.x & 3;

    const float* src = g_xcomp[dir] + ((size_t)b * RWS + rq * 4) * DI;
    for (int i = threadIdx.x; i < 4 * DI; i += 256) xs[i] = src[i];
    __syncthreads();

    const float* xpw = dir ? xpw_b : xpw_f;
    const int warp = threadIdx.x >> 5, lane = threadIdx.x & 31;
    for (int e = warp; e < 80; e += 8) {
        const float* wrow = xpw + (size_t)e * DI;
        float s0 = 0.f, s1 = 0.f, s2 = 0.f, s3 = 0.f;
        for (int k = lane; k < DI; k += 32) {
            const float w = wrow[k];
            s0 += w * xs[k];
            s1 += w * xs[DI + k];
            s2 += w * xs[2 * DI + k];
            s3 += w * xs[3 * DI + k];
        }
#pragma unroll
        for (int off = 16; off >= 1; off >>= 1) {
            s0 += __shfl_xor_sync(0xffffffffu, s0, off);
            s1 += __shfl_xor_sync(0xffffffffu, s1, off);
            s2 += __shfl_xor_sync(0xffffffffu, s2, off);
            s3 += __shfl_xor_sync(0xffffffffu, s3, off);
        }
        if (lane < 4) {
            const float v = (lane == 0) ? s0 : (lane == 1) ? s1 : (lane == 2) ? s2 : s3;
            g_xdbl[dir][((size_t)b * RWS + rq * 4 + lane) * 80 + e] = v;
        }
    }
}

// ---------------- fused dt_proj + softplus + selective scan ----------------
__global__ void __launch_bounds__(128) scan_k(const float* __restrict__ dtw_f,
                                              const float* __restrict__ dtw_b,
                                              const float* __restrict__ dtb_f,
                                              const float* __restrict__ dtb_b,
                                              const float* __restrict__ Alog_f,
                                              const float* __restrict__ Alog_b)
{
    __shared__ float xd[RWS * 80];
    __shared__ float dtws[128][49];

    const int dir = blockIdx.z;
    const int b = blockIdx.y;
    const int d0 = blockIdx.x * 128;
    const int tid = threadIdx.x;
    const int d = d0 + tid;

    const float* xdbl = g_xdbl[dir] + (size_t)b * RWS * 80;
    for (int i = tid; i < RWS * 80; i += 128) xd[i] = xdbl[i];

    const float* dtw = dir ? dtw_b : dtw_f;
    for (int idx = tid; idx < 128 * DTR; idx += 128) {
        const int row = idx / DTR, col = idx % DTR;
        dtws[row][col] = dtw[(size_t)d0 * DTR + idx];
    }
    __syncthreads();

    const float* Alog = (dir ? Alog_b : Alog_f) + (size_t)d * NS;
    const float bias = dir ? dtb_b[d] : dtb_f[d];

    float A[NS];
#pragma unroll
    for (int n = 0; n < NS; n++) A[n] = -expf(Alog[n]);

    const float A0 = A[0];
    bool chain = true;
#pragma unroll
    for (int n = 1; n < NS; n++)
        chain = chain && (fabsf(A[n] - (float)(n + 1) * A0) <= 1e-4f * fabsf(A[n]));

    float u[RWS];
    const float* up = g_xcomp[dir] + (size_t)b * RWS * DI + d;
#pragma unroll
    for (int r = 0; r < RWS; r++) u[r] = up[(size_t)r * DI];

    float h[NS];
#pragma unroll
    for (int n = 0; n < NS; n++) h[n] = 0.f;

    float* yp = g_y[dir] + (size_t)b * RWS * DI + d;
#pragma unroll 1
    for (int r = 0; r < RWS; r++) {
        float dt = bias;
#pragma unroll
        for (int rr = 0; rr < DTR; rr++) dt += xd[r * 80 + rr] * dtws[tid][rr];
        const float delta = fmaxf(dt, 0.f) + log1pf(__expf(-fabsf(dt)));
        const float du = delta * u[r];
        const float qch = __expf(delta * A0);
        float p = 1.f;
        float acc = 0.f;
#pragma unroll
        for (int n = 0; n < NS; n++) {
            float dA;
            if (chain) { p *= qch; dA = p; }
            else       { dA = __expf(delta * A[n]); }
            h[n] = dA * h[n] + du * xd[r * 80 + 48 + n];
            acc += h[n] * xd[r * 80 + 64 + n];
        }
        yp[(size_t)r * DI] = acc;
    }
}

// ---------------- combine + LayerNorm + SiLU(z) gate ----------------
__global__ void __launch_bounds__(256) ln_gate_k(const float* __restrict__ Dp,
                                                 const float* __restrict__ Dpb,
                                                 const float* __restrict__ gamma,
                                                 const float* __restrict__ beta)
{
    const int bl = blockIdx.x;
    const int b = bl >> 8;
    const int l = bl & 255;
    const int lb = 255 - l;
    const int rf = l >> 4, rb = lb >> 4;
    const int tid = threadIdx.x;

    const __half* xcf = g_xch[0] + ((size_t)b * LSEQ + l) * DI;
    const __half* xcb = g_xch[1] + ((size_t)b * LSEQ + lb) * DI;
    const float* yf = g_y[0] + ((size_t)b * RWS + rf) * DI;
    const float* yb = g_y[1] + ((size_t)b * RWS + rb) * DI;

    float v[6];
    float s = 0.f, s2 = 0.f;
#pragma unroll
    for (int i = 0; i < 6; i++) {
        const int d = tid + i * 256;
        const float cf = yf[d] + Dp[d] * __half2float(xcf[d]);
        const float cbv = yb[d] + Dpb[d] * __half2float(xcb[d]);
        const float val = 0.5f * (cf + cbv);
        v[i] = val;
        s += val;
        s2 += val * val;
    }

    __shared__ float red[16];
#pragma unroll
    for (int off = 16; off >= 1; off >>= 1) {
        s += __shfl_xor_sync(0xffffffffu, s, off);
        s2 += __shfl_xor_sync(0xffffffffu, s2, off);
    }
    const int warp = tid >> 5, lane = tid & 31;
    if (lane == 0) { red[warp] = s; red[warp + 8] = s2; }
    __syncthreads();
    if (warp == 0) {
        float a = (lane < 8) ? red[lane] : 0.f;
        float c = (lane < 8) ? red[lane + 8] : 0.f;
#pragma unroll
        for (int off = 4; off >= 1; off >>= 1) {
            a += __shfl_xor_sync(0xffffffffu, a, off);
            c += __shfl_xor_sync(0xffffffffu, c, off);
        }
        if (lane == 0) { red[0] = a; red[1] = c; }
    }
    __syncthreads();

    const float mean = red[0] * (1.f / DI);
    const float var = red[1] * (1.f / DI) - mean * mean;
    const float rstd = rsqrtf(var + 1e-5f);

#pragma unroll
    for (int i = 0; i < 6; i++) {
        const int d = tid + i * 256;
        const float g = (v[i] - mean) * rstd * gamma[d] + beta[d];
        const float zv = __half2float(g_zh[(size_t)bl * DI + d]);
        const float sz = __fdividef(zv, 1.f + __expf(-zv));
        g_gated[(size_t)bl * DI + d] = __float2half_rn(g * sz);
    }
}

// ---------------- launch ----------------
extern "C" void kernel_launch(void* const* d_in, const int* in_sizes, int n_in,
                              void* d_out, int out_size)
{
    const float* hs    = (const float*)d_in[0];
    const float* inw   = (const float*)d_in[1];
    const float* cw    = (const float*)d_in[2];
    const float* cb    = (const float*)d_in[3];
    const float* cwb   = (const float*)d_in[4];
    const float* cbb   = (const float*)d_in[5];
    const float* xpw   = (const float*)d_in[6];
    const float* xpwb  = (const float*)d_in[7];
    const float* dtw   = (const float*)d_in[8];
    const float* dtwb  = (const float*)d_in[9];
    const float* dtb   = (const float*)d_in[10];
    const float* dtbb  = (const float*)d_in[11];
    const float* Alog  = (const float*)d_in[12];
    const float* Alogb = (const float*)d_in[13];
    const float* Dp    = (const float*)d_in[14];
    const float* Dpb   = (const float*)d_in[15];
    const float* gam   = (const float*)d_in[16];
    const float* bet   = (const float*)d_in[17];
    const float* opw   = (const float*)d_in[18];
    float* out = (float*)d_out;

    __half *d_hsh, *d_wih, *d_woh;
    cudaGetSymbolAddress((void**)&d_hsh, g_hsh);
    cudaGetSymbolAddress((void**)&d_wih, g_wih);
    cudaGetSymbolAddress((void**)&d_woh, g_woh);

    cudaFuncSetAttribute(hgemm<1>, cudaFuncAttributeMaxDynamicSharedMemorySize, HG_SMEM_BYTES);
    cudaFuncSetAttribute(hgemm<2>, cudaFuncAttributeMaxDynamicSharedMemorySize, HG_SMEM_BYTES);

    // 0) convert fp32 inputs to half
    {
        const int n1 = B_SZ * LSEQ * DM / 4;      // hs
        const int n2 = 2 * DI * DM / 4;           // in_proj_w
        const int n3 = DM * DI / 4;               // out_proj_w
        f2h_k<<<(n1 + 255) / 256, 256>>>(hs, d_hsh, n1);
        f2h_k<<<(n2 + 255) / 256, 256>>>(inw, d_wih, n2);
        f2h_k<<<(n3 + 255) / 256, 256>>>(opw, d_woh, n3);
    }
    // 1) in_proj: (16384 x 768) x (3072 x 768)^T -> g_x | g_zh
    hgemm<1><<<dim3(3072 / 128, 16384 / 128), 256, HG_SMEM_BYTES>>>(nullptr, DM);
    // 2) depthwise conv + SiLU + block means
    conv_silu_k<<<dim3(DI / 16, B_SZ), 256>>>(cw, cb, cwb, cbb);
    // 3) x_proj
    xdbl_k<<<dim3(B_SZ * 4, 2), 256>>>(xpw, xpwb);
    // 4) dt_proj + selective scan
    scan_k<<<dim3(DI / 128, B_SZ, 2), 128>>>(dtw, dtwb, dtb, dtbb, Alog, Alogb);
    // 5) combine + LN + gate
    ln_gate_k<<<B_SZ * LSEQ, 256>>>(Dp, Dpb, gam, bet);
    // 6) out_proj: (16384 x 1536) x (768 x 1536)^T -> d_out
    hgemm<2><<<dim3(768 / 128, 16384 / 128), 256, HG_SMEM_BYTES>>>(out, DI);
}